// round 1
// baseline (speedup 1.0000x reference)
#include <cuda_runtime.h>

// Problem constants
#define BB 16384
#define TT 10
#define II 184
#define HH 128
#define GG 512            // 4*H
#define MM (BB*TT)        // 163840 rows for xproj GEMMs

// ---------------- device scratch (no allocations allowed) ----------------
__device__ float g_xpf[(size_t)MM * GG];      // xproj forward  (reused layer1/layer2)
__device__ float g_xpb[(size_t)MM * GG];      // xproj backward (reused layer1/layer2)
__device__ float g_o1 [(size_t)MM * 2 * HH];  // layer1 output [b][t][256]
__device__ float g_o2 [(size_t)MM * 2 * HH];  // layer2 output [b][t][256]
__device__ float g_wt [4 * GG * HH];          // transposed w_hh: [mat][k][g]

// ---------------- activation helpers ----------------
__device__ __forceinline__ float fsig(float x) {
    // 1/(1+exp(-x)) ; exp(-x)->inf for very negative x gives 0 correctly,
    // exp(-x)->0 for big x gives 1 correctly.
    return __fdividef(1.0f, 1.0f + __expf(-x));
}
__device__ __forceinline__ float ftanh(float x) {
    // tanh(x) = (e^{2x}-1)/(e^{2x}+1); clamp to avoid inf/inf
    x = fminf(x, 15.0f);
    float e = __expf(2.0f * x);
    return __fdividef(e - 1.0f, e + 1.0f);
}

// ---------------- w_hh transpose: [512][128] -> [k][512] ----------------
__global__ void transpose_whh(const float* __restrict__ w, float* __restrict__ wt) {
    int idx = blockIdx.x * 256 + threadIdx.x;   // over 512*128
    if (idx < GG * HH) {
        int g = idx / HH;
        int k = idx % HH;
        wt[(size_t)k * GG + g] = w[idx];
    }
}

// ---------------- tiled GEMM: C[M,512] = A[M,K] @ W[512,K]^T + (b1+b2) -----
// 64x64 tile, KC=16, 256 threads, 4x4 microtile per thread.
__global__ __launch_bounds__(256) void gemm_bias(
    const float* __restrict__ A, int K,
    const float* __restrict__ W,
    const float* __restrict__ b1, const float* __restrict__ b2,
    float* __restrict__ C)
{
    __shared__ float As[16][68];
    __shared__ float Ws[16][68];

    const int tid = threadIdx.x;
    const int tx  = tid & 15;       // n micro group
    const int ty  = tid >> 4;       // m micro group
    const int m0  = blockIdx.x * 64;
    const int n0  = blockIdx.y * 64;

    const int lm = tid >> 2;        // 0..63 : row this thread loads
    const int lk = (tid & 3) * 4;   // 0,4,8,12

    float acc[4][4];
#pragma unroll
    for (int i = 0; i < 4; i++)
#pragma unroll
        for (int j = 0; j < 4; j++) acc[i][j] = 0.0f;

    const float* abase = A + (size_t)(m0 + lm) * K;
    const float* wbase = W + (size_t)(n0 + lm) * K;

    for (int k0 = 0; k0 < K; k0 += 16) {
        float4 av, wv;
        if (k0 + lk + 4 <= K) {
            av = *(const float4*)(abase + k0 + lk);
            wv = *(const float4*)(wbase + k0 + lk);
        } else {
            av.x = (k0 + lk + 0 < K) ? abase[k0 + lk + 0] : 0.0f;
            av.y = (k0 + lk + 1 < K) ? abase[k0 + lk + 1] : 0.0f;
            av.z = (k0 + lk + 2 < K) ? abase[k0 + lk + 2] : 0.0f;
            av.w = (k0 + lk + 3 < K) ? abase[k0 + lk + 3] : 0.0f;
            wv.x = (k0 + lk + 0 < K) ? wbase[k0 + lk + 0] : 0.0f;
            wv.y = (k0 + lk + 1 < K) ? wbase[k0 + lk + 1] : 0.0f;
            wv.z = (k0 + lk + 2 < K) ? wbase[k0 + lk + 2] : 0.0f;
            wv.w = (k0 + lk + 3 < K) ? wbase[k0 + lk + 3] : 0.0f;
        }
        As[lk + 0][lm] = av.x; As[lk + 1][lm] = av.y;
        As[lk + 2][lm] = av.z; As[lk + 3][lm] = av.w;
        Ws[lk + 0][lm] = wv.x; Ws[lk + 1][lm] = wv.y;
        Ws[lk + 2][lm] = wv.z; Ws[lk + 3][lm] = wv.w;
        __syncthreads();

#pragma unroll
        for (int k = 0; k < 16; k++) {
            float4 a = *(const float4*)&As[k][ty * 4];
            float4 w = *(const float4*)&Ws[k][tx * 4];
            acc[0][0] += a.x * w.x; acc[0][1] += a.x * w.y; acc[0][2] += a.x * w.z; acc[0][3] += a.x * w.w;
            acc[1][0] += a.y * w.x; acc[1][1] += a.y * w.y; acc[1][2] += a.y * w.z; acc[1][3] += a.y * w.w;
            acc[2][0] += a.z * w.x; acc[2][1] += a.z * w.y; acc[2][2] += a.z * w.z; acc[2][3] += a.z * w.w;
            acc[3][0] += a.w * w.x; acc[3][1] += a.w * w.y; acc[3][2] += a.w * w.z; acc[3][3] += a.w * w.w;
        }
        __syncthreads();
    }

    // epilogue with fused bias, float4 stores (coalesced)
    const int nb = n0 + tx * 4;
    float bx = b1[nb + 0] + b2[nb + 0];
    float by = b1[nb + 1] + b2[nb + 1];
    float bz = b1[nb + 2] + b2[nb + 2];
    float bw = b1[nb + 3] + b2[nb + 3];
#pragma unroll
    for (int i = 0; i < 4; i++) {
        float4 v;
        v.x = acc[i][0] + bx; v.y = acc[i][1] + by;
        v.z = acc[i][2] + bz; v.w = acc[i][3] + bw;
        *(float4*)&C[(size_t)(m0 + ty * 4 + i) * GG + nb] = v;
    }
}

// ---------------- fused bidirectional LSTM recurrence --------------------
// gridDim = (B/32, 2). blockIdx.y = direction (0 fwd, 1 bwd).
// 32 batch rows per block, 256 threads: tx in [0,32) -> 4 hidden cols,
// ty in [0,8) -> 4 rows. 64 gate accumulators + 16 cell states per thread.
// whht layout: [k][gate*128 + hcol]  (k-major, contiguous 512 per k)
__global__ __launch_bounds__(256) void lstm_rec(
    const float* __restrict__ xp_f, const float* __restrict__ xp_b,
    const float* __restrict__ whht_base,   // 2 matrices: dir 0, dir 1
    float* __restrict__ out)               // [b][t][256], this dir writes cols dir*128..
{
    extern __shared__ float sm[];
    const int KC = 32;
    float* ws  = sm;              // KC*512 floats = 16384
    float* hsh = sm + KC * GG;    // 32*128 floats = 4096

    const int dir = blockIdx.y;
    const float* xp = dir ? xp_b : xp_f;
    const float* wt = whht_base + (size_t)dir * GG * HH;
    const int r0  = blockIdx.x * 32;
    const int tid = threadIdx.x;
    const int tx  = tid & 31;
    const int ty  = tid >> 5;
    const int j0  = tx * 4;       // hidden-col base
    const int row = ty * 4;       // local row base

    float4 c[4];
#pragma unroll
    for (int i = 0; i < 4; i++) c[i] = make_float4(0.f, 0.f, 0.f, 0.f);

    for (int i = tid; i < 32 * HH; i += 256) hsh[i] = 0.0f;
    __syncthreads();

    for (int s = 0; s < TT; s++) {
        const int t = dir ? (TT - 1 - s) : s;

        // init gates from precomputed xproj (+ both biases already folded)
        float4 acc[4][4];
#pragma unroll
        for (int i = 0; i < 4; i++) {
            size_t base = ((size_t)(r0 + row + i) * TT + t) * GG;
#pragma unroll
            for (int g = 0; g < 4; g++)
                acc[i][g] = *(const float4*)&xp[base + g * HH + j0];
        }

        // gates += h_prev @ w_hh^T
        for (int kc = 0; kc < HH; kc += KC) {
            const float4* src = (const float4*)(wt + (size_t)kc * GG);
            float4* dst = (float4*)ws;
#pragma unroll
            for (int i = 0; i < (KC * GG / 4) / 256; i++)   // 16 float4 per thread
                dst[tid + i * 256] = src[tid + i * 256];
            __syncthreads();

#pragma unroll
            for (int k = 0; k < KC; k++) {
                float h0 = hsh[(row + 0) * HH + kc + k];
                float h1 = hsh[(row + 1) * HH + kc + k];
                float h2 = hsh[(row + 2) * HH + kc + k];
                float h3 = hsh[(row + 3) * HH + kc + k];
#pragma unroll
                for (int g = 0; g < 4; g++) {
                    float4 w = *(const float4*)&ws[k * GG + g * HH + j0];
                    acc[0][g].x += h0 * w.x; acc[0][g].y += h0 * w.y; acc[0][g].z += h0 * w.z; acc[0][g].w += h0 * w.w;
                    acc[1][g].x += h1 * w.x; acc[1][g].y += h1 * w.y; acc[1][g].z += h1 * w.z; acc[1][g].w += h1 * w.w;
                    acc[2][g].x += h2 * w.x; acc[2][g].y += h2 * w.y; acc[2][g].z += h2 * w.z; acc[2][g].w += h2 * w.w;
                    acc[3][g].x += h3 * w.x; acc[3][g].y += h3 * w.y; acc[3][g].z += h3 * w.z; acc[3][g].w += h3 * w.w;
                }
            }
            __syncthreads();
        }

        // activations + state update + emit h
        float4 hv[4];
#pragma unroll
        for (int i = 0; i < 4; i++) {
            float4 ig, fg, gg, og;
            ig.x = fsig(acc[i][0].x); ig.y = fsig(acc[i][0].y); ig.z = fsig(acc[i][0].z); ig.w = fsig(acc[i][0].w);
            fg.x = fsig(acc[i][1].x); fg.y = fsig(acc[i][1].y); fg.z = fsig(acc[i][1].z); fg.w = fsig(acc[i][1].w);
            gg.x = ftanh(acc[i][2].x); gg.y = ftanh(acc[i][2].y); gg.z = ftanh(acc[i][2].z); gg.w = ftanh(acc[i][2].w);
            og.x = fsig(acc[i][3].x); og.y = fsig(acc[i][3].y); og.z = fsig(acc[i][3].z); og.w = fsig(acc[i][3].w);

            c[i].x = fg.x * c[i].x + ig.x * gg.x;
            c[i].y = fg.y * c[i].y + ig.y * gg.y;
            c[i].z = fg.z * c[i].z + ig.z * gg.z;
            c[i].w = fg.w * c[i].w + ig.w * gg.w;

            hv[i].x = og.x * ftanh(c[i].x);
            hv[i].y = og.y * ftanh(c[i].y);
            hv[i].z = og.z * ftanh(c[i].z);
            hv[i].w = og.w * ftanh(c[i].w);

            size_t ob = ((size_t)(r0 + row + i) * TT + t) * (2 * HH) + dir * HH + j0;
            *(float4*)&out[ob] = hv[i];
        }
        // safe: all threads passed the final chunk __syncthreads before anyone writes
#pragma unroll
        for (int i = 0; i < 4; i++)
            *(float4*)&hsh[(row + i) * HH + j0] = hv[i];
        __syncthreads();
    }
}

// ---------------- fused maxpool(T) + FC(512->64) + ReLU + FC(64->1) -------
// one warp per batch row; fc1_w staged in shared (pitch 517 = conflict-free)
#define W1PITCH 517
__global__ __launch_bounds__(256) void pool_fc(
    const float* __restrict__ o2,
    const float* __restrict__ fc1w, const float* __restrict__ fc1b,
    const float* __restrict__ fc2w, const float* __restrict__ fc2b,
    float* __restrict__ y, int rows_per_warp)
{
    extern __shared__ float sm[];
    float* w1    = sm;                 // 64 * 517
    float* feats = sm + 64 * W1PITCH;  // 8 warps * 512

    for (int i = threadIdx.x; i < 64 * 512; i += 256) {
        int j = i >> 9, f = i & 511;
        w1[j * W1PITCH + f] = fc1w[i];
    }
    __syncthreads();

    const int wid  = threadIdx.x >> 5;
    const int lane = threadIdx.x & 31;
    float* myfeat = feats + wid * 512;

    for (int it = 0; it < rows_per_warp; it++) {
        int b = blockIdx.x * (8 * rows_per_warp) + it * 8 + wid;

        // max-pool over two segments of 5 timesteps; feature idx = c*2 + seg
#pragma unroll
        for (int q = 0; q < 8; q++) {
            int cc = lane + q * 32;
            float m0 = -3.4e38f, m1 = -3.4e38f;
#pragma unroll
            for (int t = 0; t < 5; t++)
                m0 = fmaxf(m0, o2[((size_t)b * TT + t) * (2 * HH) + cc]);
#pragma unroll
            for (int t = 5; t < 10; t++)
                m1 = fmaxf(m1, o2[((size_t)b * TT + t) * (2 * HH) + cc]);
            myfeat[cc * 2 + 0] = m0;
            myfeat[cc * 2 + 1] = m1;
        }
        __syncwarp();

        // fc1: lane computes outputs j = lane and lane+32
        float a0 = fc1b[lane];
        float a1 = fc1b[lane + 32];
        const float* wr0 = &w1[lane * W1PITCH];
        const float* wr1 = &w1[(lane + 32) * W1PITCH];
#pragma unroll 8
        for (int f = 0; f < 512; f++) {
            float v = myfeat[f];
            a0 += v * wr0[f];
            a1 += v * wr1[f];
        }
        a0 = fmaxf(a0, 0.0f);
        a1 = fmaxf(a1, 0.0f);

        float p = a0 * fc2w[lane] + a1 * fc2w[lane + 32];
#pragma unroll
        for (int off = 16; off; off >>= 1)
            p += __shfl_down_sync(0xffffffffu, p, off);
        if (lane == 0) y[b] = p + fc2b[0];
        __syncwarp();
    }
}

// ---------------- launch ----------------
extern "C" void kernel_launch(void* const* d_in, const int* in_sizes, int n_in,
                              void* d_out, int out_size)
{
    const float* x       = (const float*)d_in[0];
    const float* w_ih1_f = (const float*)d_in[1];
    const float* w_hh1_f = (const float*)d_in[2];
    const float* b_ih1_f = (const float*)d_in[3];
    const float* b_hh1_f = (const float*)d_in[4];
    const float* w_ih1_b = (const float*)d_in[5];
    const float* w_hh1_b = (const float*)d_in[6];
    const float* b_ih1_b = (const float*)d_in[7];
    const float* b_hh1_b = (const float*)d_in[8];
    const float* w_ih2_f = (const float*)d_in[9];
    const float* w_hh2_f = (const float*)d_in[10];
    const float* b_ih2_f = (const float*)d_in[11];
    const float* b_hh2_f = (const float*)d_in[12];
    const float* w_ih2_b = (const float*)d_in[13];
    const float* w_hh2_b = (const float*)d_in[14];
    const float* b_ih2_b = (const float*)d_in[15];
    const float* b_hh2_b = (const float*)d_in[16];
    const float* fc1_w   = (const float*)d_in[17];
    const float* fc1_b   = (const float*)d_in[18];
    const float* fc2_w   = (const float*)d_in[19];
    const float* fc2_b   = (const float*)d_in[20];
    float* y = (float*)d_out;

    float *xpf, *xpb, *o1, *o2, *wt;
    cudaGetSymbolAddress((void**)&xpf, g_xpf);
    cudaGetSymbolAddress((void**)&xpb, g_xpb);
    cudaGetSymbolAddress((void**)&o1,  g_o1);
    cudaGetSymbolAddress((void**)&o2,  g_o2);
    cudaGetSymbolAddress((void**)&wt,  g_wt);

    const int recSmem  = (32 * GG + 32 * HH) * 4;              // 81920 B
    const int poolSmem = (64 * W1PITCH + 8 * 512) * 4;          // 148736 B
    cudaFuncSetAttribute(lstm_rec, cudaFuncAttributeMaxDynamicSharedMemorySize, recSmem);
    cudaFuncSetAttribute(pool_fc,  cudaFuncAttributeMaxDynamicSharedMemorySize, poolSmem);

    // 1) transpose the four w_hh matrices into k-major layout
    transpose_whh<<<256, 256>>>(w_hh1_f, wt + 0 * GG * HH);
    transpose_whh<<<256, 256>>>(w_hh1_b, wt + 1 * GG * HH);
    transpose_whh<<<256, 256>>>(w_hh2_f, wt + 2 * GG * HH);
    transpose_whh<<<256, 256>>>(w_hh2_b, wt + 3 * GG * HH);

    dim3 gemmGrid(MM / 64, GG / 64);   // (2560, 8)

    // 2) layer 1 xproj (K = 184)
    gemm_bias<<<gemmGrid, 256>>>(x, II, w_ih1_f, b_ih1_f, b_hh1_f, xpf);
    gemm_bias<<<gemmGrid, 256>>>(x, II, w_ih1_b, b_ih1_b, b_hh1_b, xpb);

    // 3) layer 1 recurrence (both directions)
    lstm_rec<<<dim3(BB / 32, 2), 256, recSmem>>>(xpf, xpb, wt, o1);

    // 4) layer 2 xproj (K = 256, input = layer1 output)
    gemm_bias<<<gemmGrid, 256>>>(o1, 2 * HH, w_ih2_f, b_ih2_f, b_hh2_f, xpf);
    gemm_bias<<<gemmGrid, 256>>>(o1, 2 * HH, w_ih2_b, b_ih2_b, b_hh2_b, xpb);

    // 5) layer 2 recurrence
    lstm_rec<<<dim3(BB / 32, 2), 256, recSmem>>>(xpf, xpb, wt + 2 * GG * HH, o2);

    // 6) pool + FC head
    pool_fc<<<256, 256, poolSmem>>>(o2, fc1_w, fc1_b, fc2_w, fc2_b, y, 8);
}

// round 3
// speedup vs baseline: 1.4698x; 1.4698x over previous
#include <cuda_runtime.h>
#include <cuda_bf16.h>
#include <cstdint>

// Problem constants
#define BB 16384
#define TT 10
#define II 184
#define HH 128
#define GG 512            // 4*H
#define MM (BB*TT)        // 163840 rows for xproj GEMMs
#define K1P 192           // layer-1 K padded (184 -> 192)
#define K2P 256           // layer-2 K

// ---------------- device scratch (no allocations allowed) ----------------
__device__ float g_xpf[(size_t)MM * GG];
__device__ float g_xpb[(size_t)MM * GG];
__device__ float g_o2 [(size_t)MM * 2 * HH];
__device__ __nv_bfloat16 g_xhi[(size_t)MM * K1P];
__device__ __nv_bfloat16 g_xlo[(size_t)MM * K1P];
__device__ __nv_bfloat16 g_ohi[(size_t)MM * K2P];
__device__ __nv_bfloat16 g_olo[(size_t)MM * K2P];
__device__ __nv_bfloat16 g_whi[4 * (size_t)GG * K2P];
__device__ __nv_bfloat16 g_wlo[4 * (size_t)GG * K2P];
__device__ float g_wt [4 * GG * HH];

// ---------------- small PTX helpers ----------------
__device__ __forceinline__ uint32_t smem_u32(const void* p) {
    uint32_t a;
    asm("{ .reg .u64 t; cvta.to.shared.u64 t, %1; cvt.u32.u64 %0, t; }" : "=r"(a) : "l"(p));
    return a;
}
__device__ __forceinline__ void ldm_x4(uint32_t& r0, uint32_t& r1, uint32_t& r2, uint32_t& r3,
                                       uint32_t addr) {
    asm volatile("ldmatrix.sync.aligned.m8n8.x4.shared.b16 {%0,%1,%2,%3}, [%4];"
                 : "=r"(r0), "=r"(r1), "=r"(r2), "=r"(r3) : "r"(addr));
}
__device__ __forceinline__ void mma_bf16(float* c, const uint32_t* a, const uint32_t* b) {
    asm volatile(
        "mma.sync.aligned.m16n8k16.row.col.f32.bf16.bf16.f32 "
        "{%0,%1,%2,%3}, {%4,%5,%6,%7}, {%8,%9}, {%0,%1,%2,%3};"
        : "+f"(c[0]), "+f"(c[1]), "+f"(c[2]), "+f"(c[3])
        : "r"(a[0]), "r"(a[1]), "r"(a[2]), "r"(a[3]), "r"(b[0]), "r"(b[1]));
}

// ---------------- activation helpers ----------------
__device__ __forceinline__ float fsig(float x) {
    return __fdividef(1.0f, 1.0f + __expf(-x));
}
__device__ __forceinline__ float ftanh(float x) {
    x = fminf(x, 15.0f);
    float e = __expf(2.0f * x);
    return __fdividef(e - 1.0f, e + 1.0f);
}

// ---------------- fp32 -> bf16 hi/lo split (with K zero-padding) ----------
__global__ void convert_split(const float* __restrict__ src,
                              __nv_bfloat16* __restrict__ dhi,
                              __nv_bfloat16* __restrict__ dlo,
                              unsigned rows, unsigned Ksrc, unsigned Kpad)
{
    unsigned total = rows * Kpad;
    for (unsigned idx = blockIdx.x * blockDim.x + threadIdx.x; idx < total;
         idx += gridDim.x * blockDim.x) {
        unsigned row = idx / Kpad;
        unsigned k = idx - row * Kpad;
        float v = (k < Ksrc) ? src[(size_t)row * Ksrc + k] : 0.0f;
        __nv_bfloat16 h = __float2bfloat16_rn(v);
        dhi[idx] = h;
        dlo[idx] = __float2bfloat16_rn(v - __bfloat162float(h));
    }
}

// ---------------- w_hh transpose: [512][128] -> [k][512] ----------------
__global__ void transpose_whh(const float* __restrict__ w, float* __restrict__ wt) {
    int idx = blockIdx.x * 256 + threadIdx.x;
    if (idx < GG * HH) {
        int g = idx / HH;
        int k = idx % HH;
        wt[(size_t)k * GG + g] = w[idx];
    }
}

// ---------------- split-bf16 GEMM via mma.sync (HMMA) --------------------
// C[M,512] = A[M,K] @ W[512,K]^T + (b1+b2).
// CTA tile 128x128, 8 warps 4(M)x2(N), warp tile 32x64. K chunks of 64.
#define PIT 72          // smem row pitch in bf16 elems (144B) -> conflict-free ldmatrix
#define PITB 144
__global__ __launch_bounds__(256) void gemm_mma(
    const __nv_bfloat16* __restrict__ a_hi, const __nv_bfloat16* __restrict__ a_lo,
    const __nv_bfloat16* __restrict__ w_hi, const __nv_bfloat16* __restrict__ w_lo,
    int Kpad, int nchunks,
    const float* __restrict__ b1, const float* __restrict__ b2,
    float* __restrict__ C)
{
    extern __shared__ __nv_bfloat16 sm[];
    __nv_bfloat16* sAh = sm;
    __nv_bfloat16* sAl = sm + 128 * PIT;
    __nv_bfloat16* sBh = sm + 2 * 128 * PIT;
    __nv_bfloat16* sBl = sm + 3 * 128 * PIT;
    float* sbias = (float*)(sm + 4 * 128 * PIT);

    const int tid  = threadIdx.x;
    const int wid  = tid >> 5;
    const int lane = tid & 31;
    const int wm   = wid & 3;      // 0..3 -> M offset wm*32
    const int wn   = wid >> 2;     // 0..1 -> N offset wn*64
    const int m0   = blockIdx.x * 128;
    const int n0   = blockIdx.y * 128;

    if (tid < 128) sbias[tid] = b1[n0 + tid] + b2[n0 + tid];

    const uint32_t sbAh = smem_u32(sAh), sbAl = smem_u32(sAl);
    const uint32_t sbBh = smem_u32(sBh), sbBl = smem_u32(sBl);

    // per-lane ldmatrix byte offsets
    const uint32_t aoff = (uint32_t)(lane & 15) * PITB + (uint32_t)(lane >> 4) * 16;
    const uint32_t boff = ((uint32_t)((lane & 7) + ((lane >> 4) << 3))) * PITB
                        + (uint32_t)((lane >> 3) & 1) * 16;

    float acc[2][8][4];
#pragma unroll
    for (int mt = 0; mt < 2; mt++)
#pragma unroll
        for (int nt = 0; nt < 8; nt++)
#pragma unroll
            for (int q = 0; q < 4; q++) acc[mt][nt][q] = 0.0f;

    for (int c = 0; c < nchunks; c++) {
        const int kb = c * 64;
        // stage A/B hi+lo tiles: 128 rows x 64 bf16 each
#pragma unroll
        for (int i = 0; i < 4; i++) {
            int idx = tid + i * 256;       // 0..1023
            int row = idx >> 3, f4 = idx & 7;
            *(float4*)&sAh[row * PIT + f4 * 8] =
                *(const float4*)(a_hi + (size_t)(m0 + row) * Kpad + kb + f4 * 8);
            *(float4*)&sAl[row * PIT + f4 * 8] =
                *(const float4*)(a_lo + (size_t)(m0 + row) * Kpad + kb + f4 * 8);
            *(float4*)&sBh[row * PIT + f4 * 8] =
                *(const float4*)(w_hi + (size_t)(n0 + row) * Kpad + kb + f4 * 8);
            *(float4*)&sBl[row * PIT + f4 * 8] =
                *(const float4*)(w_lo + (size_t)(n0 + row) * Kpad + kb + f4 * 8);
        }
        __syncthreads();

#pragma unroll
        for (int ks = 0; ks < 4; ks++) {
            const uint32_t kbyte = (uint32_t)(ks * 32);   // k16 slab within chunk

            uint32_t ah[2][4], al[2][4];
#pragma unroll
            for (int mt = 0; mt < 2; mt++) {
                uint32_t rbase = (uint32_t)(wm * 32 + mt * 16) * PITB + aoff + kbyte;
                ldm_x4(ah[mt][0], ah[mt][1], ah[mt][2], ah[mt][3], sbAh + rbase);
                ldm_x4(al[mt][0], al[mt][1], al[mt][2], al[mt][3], sbAl + rbase);
            }

#pragma unroll
            for (int half = 0; half < 2; half++) {
                uint32_t bh[4][2], bl[4][2];
#pragma unroll
                for (int p = 0; p < 2; p++) {
                    uint32_t nb = (uint32_t)(wn * 64 + half * 32 + p * 16) * PITB + boff + kbyte;
                    ldm_x4(bh[2*p][0], bh[2*p][1], bh[2*p+1][0], bh[2*p+1][1], sbBh + nb);
                    ldm_x4(bl[2*p][0], bl[2*p][1], bl[2*p+1][0], bl[2*p+1][1], sbBl + nb);
                }
#pragma unroll
                for (int mt = 0; mt < 2; mt++)
#pragma unroll
                    for (int nt = 0; nt < 4; nt++) {
                        float* cc = acc[mt][half * 4 + nt];
                        mma_bf16(cc, ah[mt], bh[nt]);   // hi*hi
                        mma_bf16(cc, ah[mt], bl[nt]);   // hi*lo
                        mma_bf16(cc, al[mt], bh[nt]);   // lo*hi
                    }
            }
        }
        __syncthreads();
    }

    // epilogue: c0=C[g][2t], c1=C[g][2t+1], c2=C[g+8][2t], c3=C[g+8][2t+1]
    const int g = lane >> 2, t = lane & 3;
#pragma unroll
    for (int mt = 0; mt < 2; mt++) {
        const int row0 = m0 + wm * 32 + mt * 16 + g;
#pragma unroll
        for (int nt = 0; nt < 8; nt++) {
            const int cl = wn * 64 + nt * 8 + 2 * t;   // col within CTA
            float2 v0, v1;
            v0.x = acc[mt][nt][0] + sbias[cl];
            v0.y = acc[mt][nt][1] + sbias[cl + 1];
            v1.x = acc[mt][nt][2] + sbias[cl];
            v1.y = acc[mt][nt][3] + sbias[cl + 1];
            *(float2*)&C[(size_t)row0 * GG + n0 + cl] = v0;
            *(float2*)&C[(size_t)(row0 + 8) * GG + n0 + cl] = v1;
        }
    }
}

// ---------------- fused bidirectional LSTM recurrence --------------------
__global__ __launch_bounds__(256) void lstm_rec(
    const float* __restrict__ xp_f, const float* __restrict__ xp_b,
    const float* __restrict__ whht_base,
    float* __restrict__ out32,
    __nv_bfloat16* __restrict__ ohi, __nv_bfloat16* __restrict__ olo)
{
    extern __shared__ float smf[];
    const int KC = 32;
    float* ws  = smf;
    float* hsh = smf + KC * GG;

    const int dir = blockIdx.y;
    const float* xp = dir ? xp_b : xp_f;
    const float* wt = whht_base + (size_t)dir * GG * HH;
    const int r0  = blockIdx.x * 32;
    const int tid = threadIdx.x;
    const int tx  = tid & 31;
    const int ty  = tid >> 5;
    const int j0  = tx * 4;
    const int row = ty * 4;

    float4 c[4];
#pragma unroll
    for (int i = 0; i < 4; i++) c[i] = make_float4(0.f, 0.f, 0.f, 0.f);

    for (int i = tid; i < 32 * HH; i += 256) hsh[i] = 0.0f;
    __syncthreads();

    for (int s = 0; s < TT; s++) {
        const int t = dir ? (TT - 1 - s) : s;

        float4 acc[4][4];
#pragma unroll
        for (int i = 0; i < 4; i++) {
            size_t base = ((size_t)(r0 + row + i) * TT + t) * GG;
#pragma unroll
            for (int g = 0; g < 4; g++)
                acc[i][g] = *(const float4*)&xp[base + g * HH + j0];
        }

        for (int kc = 0; kc < HH; kc += KC) {
            const float4* src = (const float4*)(wt + (size_t)kc * GG);
            float4* dst = (float4*)ws;
#pragma unroll
            for (int i = 0; i < (KC * GG / 4) / 256; i++)
                dst[tid + i * 256] = src[tid + i * 256];
            __syncthreads();

#pragma unroll
            for (int k = 0; k < KC; k++) {
                float h0 = hsh[(row + 0) * HH + kc + k];
                float h1 = hsh[(row + 1) * HH + kc + k];
                float h2 = hsh[(row + 2) * HH + kc + k];
                float h3 = hsh[(row + 3) * HH + kc + k];
#pragma unroll
                for (int g = 0; g < 4; g++) {
                    float4 w = *(const float4*)&ws[k * GG + g * HH + j0];
                    acc[0][g].x += h0 * w.x; acc[0][g].y += h0 * w.y; acc[0][g].z += h0 * w.z; acc[0][g].w += h0 * w.w;
                    acc[1][g].x += h1 * w.x; acc[1][g].y += h1 * w.y; acc[1][g].z += h1 * w.z; acc[1][g].w += h1 * w.w;
                    acc[2][g].x += h2 * w.x; acc[2][g].y += h2 * w.y; acc[2][g].z += h2 * w.z; acc[2][g].w += h2 * w.w;
                    acc[3][g].x += h3 * w.x; acc[3][g].y += h3 * w.y; acc[3][g].z += h3 * w.z; acc[3][g].w += h3 * w.w;
                }
            }
            __syncthreads();
        }

        float4 hv[4];
#pragma unroll
        for (int i = 0; i < 4; i++) {
            float4 ig, fg, gg, og;
            ig.x = fsig(acc[i][0].x); ig.y = fsig(acc[i][0].y); ig.z = fsig(acc[i][0].z); ig.w = fsig(acc[i][0].w);
            fg.x = fsig(acc[i][1].x); fg.y = fsig(acc[i][1].y); fg.z = fsig(acc[i][1].z); fg.w = fsig(acc[i][1].w);
            gg.x = ftanh(acc[i][2].x); gg.y = ftanh(acc[i][2].y); gg.z = ftanh(acc[i][2].z); gg.w = ftanh(acc[i][2].w);
            og.x = fsig(acc[i][3].x); og.y = fsig(acc[i][3].y); og.z = fsig(acc[i][3].z); og.w = fsig(acc[i][3].w);

            c[i].x = fg.x * c[i].x + ig.x * gg.x;
            c[i].y = fg.y * c[i].y + ig.y * gg.y;
            c[i].z = fg.z * c[i].z + ig.z * gg.z;
            c[i].w = fg.w * c[i].w + ig.w * gg.w;

            hv[i].x = og.x * ftanh(c[i].x);
            hv[i].y = og.y * ftanh(c[i].y);
            hv[i].z = og.z * ftanh(c[i].z);
            hv[i].w = og.w * ftanh(c[i].w);

            size_t ob = ((size_t)(r0 + row + i) * TT + t) * (2 * HH) + dir * HH + j0;
            if (out32) {
                *(float4*)&out32[ob] = hv[i];
            } else {
                float4 v = hv[i];
                __nv_bfloat16 hx = __float2bfloat16_rn(v.x);
                __nv_bfloat16 hy = __float2bfloat16_rn(v.y);
                __nv_bfloat16 hz = __float2bfloat16_rn(v.z);
                __nv_bfloat16 hw = __float2bfloat16_rn(v.w);
                __nv_bfloat162 p01; p01.x = hx; p01.y = hy;
                __nv_bfloat162 p23; p23.x = hz; p23.y = hw;
                uint2 uu;
                uu.x = *reinterpret_cast<unsigned*>(&p01);
                uu.y = *reinterpret_cast<unsigned*>(&p23);
                *reinterpret_cast<uint2*>(&ohi[ob]) = uu;

                __nv_bfloat162 q01, q23;
                q01.x = __float2bfloat16_rn(v.x - __bfloat162float(hx));
                q01.y = __float2bfloat16_rn(v.y - __bfloat162float(hy));
                q23.x = __float2bfloat16_rn(v.z - __bfloat162float(hz));
                q23.y = __float2bfloat16_rn(v.w - __bfloat162float(hw));
                uint2 ll;
                ll.x = *reinterpret_cast<unsigned*>(&q01);
                ll.y = *reinterpret_cast<unsigned*>(&q23);
                *reinterpret_cast<uint2*>(&olo[ob]) = ll;
            }
        }
#pragma unroll
        for (int i = 0; i < 4; i++)
            *(float4*)&hsh[(row + i) * HH + j0] = hv[i];
        __syncthreads();
    }
}

// ---------------- fused maxpool(T) + FC(512->64) + ReLU + FC(64->1) -------
#define W1PITCH 517
__global__ __launch_bounds__(256) void pool_fc(
    const float* __restrict__ o2,
    const float* __restrict__ fc1w, const float* __restrict__ fc1b,
    const float* __restrict__ fc2w, const float* __restrict__ fc2b,
    float* __restrict__ y, int rows_per_warp)
{
    extern __shared__ float smf[];
    float* w1    = smf;
    float* feats = smf + 64 * W1PITCH;

    for (int i = threadIdx.x; i < 64 * 512; i += 256) {
        int j = i >> 9, f = i & 511;
        w1[j * W1PITCH + f] = fc1w[i];
    }
    __syncthreads();

    const int wid  = threadIdx.x >> 5;
    const int lane = threadIdx.x & 31;
    float* myfeat = feats + wid * 512;

    for (int it = 0; it < rows_per_warp; it++) {
        int b = blockIdx.x * (8 * rows_per_warp) + it * 8 + wid;

#pragma unroll
        for (int q = 0; q < 8; q++) {
            int cc = lane + q * 32;
            float m0 = -3.4e38f, m1 = -3.4e38f;
#pragma unroll
            for (int t = 0; t < 5; t++)
                m0 = fmaxf(m0, o2[((size_t)b * TT + t) * (2 * HH) + cc]);
#pragma unroll
            for (int t = 5; t < 10; t++)
                m1 = fmaxf(m1, o2[((size_t)b * TT + t) * (2 * HH) + cc]);
            myfeat[cc * 2 + 0] = m0;
            myfeat[cc * 2 + 1] = m1;
        }
        __syncwarp();

        float a0 = fc1b[lane];
        float a1 = fc1b[lane + 32];
        const float* wr0 = &w1[lane * W1PITCH];
        const float* wr1 = &w1[(lane + 32) * W1PITCH];
#pragma unroll 8
        for (int f = 0; f < 512; f++) {
            float v = myfeat[f];
            a0 += v * wr0[f];
            a1 += v * wr1[f];
        }
        a0 = fmaxf(a0, 0.0f);
        a1 = fmaxf(a1, 0.0f);

        float p = a0 * fc2w[lane] + a1 * fc2w[lane + 32];
#pragma unroll
        for (int off = 16; off; off >>= 1)
            p += __shfl_down_sync(0xffffffffu, p, off);
        if (lane == 0) y[b] = p + fc2b[0];
        __syncwarp();
    }
}

// ---------------- launch ----------------
extern "C" void kernel_launch(void* const* d_in, const int* in_sizes, int n_in,
                              void* d_out, int out_size)
{
    const float* x       = (const float*)d_in[0];
    const float* w_ih1_f = (const float*)d_in[1];
    const float* w_hh1_f = (const float*)d_in[2];
    const float* b_ih1_f = (const float*)d_in[3];
    const float* b_hh1_f = (const float*)d_in[4];
    const float* w_ih1_b = (const float*)d_in[5];
    const float* w_hh1_b = (const float*)d_in[6];
    const float* b_ih1_b = (const float*)d_in[7];
    const float* b_hh1_b = (const float*)d_in[8];
    const float* w_ih2_f = (const float*)d_in[9];
    const float* w_hh2_f = (const float*)d_in[10];
    const float* b_ih2_f = (const float*)d_in[11];
    const float* b_hh2_f = (const float*)d_in[12];
    const float* w_ih2_b = (const float*)d_in[13];
    const float* w_hh2_b = (const float*)d_in[14];
    const float* b_ih2_b = (const float*)d_in[15];
    const float* b_hh2_b = (const float*)d_in[16];
    const float* fc1_w   = (const float*)d_in[17];
    const float* fc1_b   = (const float*)d_in[18];
    const float* fc2_w   = (const float*)d_in[19];
    const float* fc2_b   = (const float*)d_in[20];
    float* y = (float*)d_out;

    float *xpf, *xpb, *o2, *wt;
    __nv_bfloat16 *xhi, *xlo, *ohi, *olo, *whi, *wlo;
    cudaGetSymbolAddress((void**)&xpf, g_xpf);
    cudaGetSymbolAddress((void**)&xpb, g_xpb);
    cudaGetSymbolAddress((void**)&o2,  g_o2);
    cudaGetSymbolAddress((void**)&wt,  g_wt);
    cudaGetSymbolAddress((void**)&xhi, g_xhi);
    cudaGetSymbolAddress((void**)&xlo, g_xlo);
    cudaGetSymbolAddress((void**)&ohi, g_ohi);
    cudaGetSymbolAddress((void**)&olo, g_olo);
    cudaGetSymbolAddress((void**)&whi, g_whi);
    cudaGetSymbolAddress((void**)&wlo, g_wlo);

    const int recSmem  = (32 * GG + 32 * HH) * 4;               // 81920 B
    const int poolSmem = (64 * W1PITCH + 8 * 512) * 4;           // 148736 B
    const int gemmSmem = 4 * 128 * PIT * 2 + 128 * 4;            // 74240 B
    cudaFuncSetAttribute(lstm_rec, cudaFuncAttributeMaxDynamicSharedMemorySize, recSmem);
    cudaFuncSetAttribute(pool_fc,  cudaFuncAttributeMaxDynamicSharedMemorySize, poolSmem);
    cudaFuncSetAttribute(gemm_mma, cudaFuncAttributeMaxDynamicSharedMemorySize, gemmSmem);

    const size_t WSLOT = (size_t)GG * K2P;
    dim3 gemmGrid(MM / 128, GG / 128);   // (1280, 4)

    // 0-4) split conversions (x + the 4 w_ih matrices)
    convert_split<<<16384, 256>>>(x, xhi, xlo, MM, II, K1P);
    convert_split<<<512, 256>>>(w_ih1_f, whi + 0 * WSLOT, wlo + 0 * WSLOT, GG, II, K1P);
    convert_split<<<512, 256>>>(w_ih1_b, whi + 1 * WSLOT, wlo + 1 * WSLOT, GG, II, K1P);
    convert_split<<<512, 256>>>(w_ih2_f, whi + 2 * WSLOT, wlo + 2 * WSLOT, GG, 2 * HH, K2P);
    convert_split<<<512, 256>>>(w_ih2_b, whi + 3 * WSLOT, wlo + 3 * WSLOT, GG, 2 * HH, K2P);

    // 5-6) layer 1 xproj (HMMA, K=192) — launch #5 is the ncu capture target
    gemm_mma<<<gemmGrid, 256, gemmSmem>>>(xhi, xlo, whi + 0 * WSLOT, wlo + 0 * WSLOT,
                                          K1P, 3, b_ih1_f, b_hh1_f, xpf);
    gemm_mma<<<gemmGrid, 256, gemmSmem>>>(xhi, xlo, whi + 1 * WSLOT, wlo + 1 * WSLOT,
                                          K1P, 3, b_ih1_b, b_hh1_b, xpb);

    // 7-10) w_hh transposes for the recurrence
    transpose_whh<<<256, 256>>>(w_hh1_f, wt + 0 * GG * HH);
    transpose_whh<<<256, 256>>>(w_hh1_b, wt + 1 * GG * HH);
    transpose_whh<<<256, 256>>>(w_hh2_f, wt + 2 * GG * HH);
    transpose_whh<<<256, 256>>>(w_hh2_b, wt + 3 * GG * HH);

    // 11) layer 1 recurrence -> bf16 hi/lo output (feeds layer-2 GEMM)
    lstm_rec<<<dim3(BB / 32, 2), 256, recSmem>>>(xpf, xpb, wt, (float*)nullptr, ohi, olo);

    // 12-13) layer 2 xproj (K=256)
    gemm_mma<<<gemmGrid, 256, gemmSmem>>>(ohi, olo, whi + 2 * WSLOT, wlo + 2 * WSLOT,
                                          K2P, 4, b_ih2_f, b_hh2_f, xpf);
    gemm_mma<<<gemmGrid, 256, gemmSmem>>>(ohi, olo, whi + 3 * WSLOT, wlo + 3 * WSLOT,
                                          K2P, 4, b_ih2_b, b_hh2_b, xpb);

    // 14) layer 2 recurrence -> fp32 output
    lstm_rec<<<dim3(BB / 32, 2), 256, recSmem>>>(xpf, xpb, wt + 2 * GG * HH, o2,
                                                 (__nv_bfloat16*)nullptr, (__nv_bfloat16*)nullptr);

    // 15) pool + FC head
    pool_fc<<<256, 256, poolSmem>>>(o2, fc1_w, fc1_b, fc2_w, fc2_b, y, 8);
}

// round 4
// speedup vs baseline: 1.8798x; 1.2789x over previous
#include <cuda_runtime.h>
#include <cuda_bf16.h>
#include <cstdint>

// Problem constants
#define BB 16384
#define TT 10
#define II 184
#define HH 128
#define GG 512            // 4*H
#define MM (BB*TT)        // 163840 rows for xproj GEMMs
#define K1P 192           // layer-1 K padded (184 -> 192)
#define K2P 256           // layer-2 K

// ---------------- device scratch (no allocations allowed) ----------------
__device__ float g_xpf[(size_t)MM * GG];
__device__ float g_xpb[(size_t)MM * GG];
__device__ float g_o2 [(size_t)MM * 2 * HH];
__device__ __nv_bfloat16 g_xhi[(size_t)MM * K1P];
__device__ __nv_bfloat16 g_xlo[(size_t)MM * K1P];
__device__ __nv_bfloat16 g_ohi[(size_t)MM * K2P];
__device__ __nv_bfloat16 g_olo[(size_t)MM * K2P];
__device__ __nv_bfloat16 g_whi[4 * (size_t)GG * K2P];
__device__ __nv_bfloat16 g_wlo[4 * (size_t)GG * K2P];
__device__ __nv_bfloat16 g_whhhi[4 * (size_t)GG * HH];   // w_hh bf16 hi (4 slots)
__device__ __nv_bfloat16 g_whhlo[4 * (size_t)GG * HH];   // w_hh bf16 lo

// ---------------- small PTX helpers ----------------
__device__ __forceinline__ uint32_t smem_u32(const void* p) {
    uint32_t a;
    asm("{ .reg .u64 t; cvta.to.shared.u64 t, %1; cvt.u32.u64 %0, t; }" : "=r"(a) : "l"(p));
    return a;
}
__device__ __forceinline__ void ldm_x4(uint32_t& r0, uint32_t& r1, uint32_t& r2, uint32_t& r3,
                                       uint32_t addr) {
    asm volatile("ldmatrix.sync.aligned.m8n8.x4.shared.b16 {%0,%1,%2,%3}, [%4];"
                 : "=r"(r0), "=r"(r1), "=r"(r2), "=r"(r3) : "r"(addr));
}
__device__ __forceinline__ void mma_bf16(float* c, const uint32_t* a, const uint32_t* b) {
    asm volatile(
        "mma.sync.aligned.m16n8k16.row.col.f32.bf16.bf16.f32 "
        "{%0,%1,%2,%3}, {%4,%5,%6,%7}, {%8,%9}, {%0,%1,%2,%3};"
        : "+f"(c[0]), "+f"(c[1]), "+f"(c[2]), "+f"(c[3])
        : "r"(a[0]), "r"(a[1]), "r"(a[2]), "r"(a[3]), "r"(b[0]), "r"(b[1]));
}
__device__ __forceinline__ void cp16(uint32_t dst, const void* src) {
    asm volatile("cp.async.cg.shared.global [%0], [%1], 16;" :: "r"(dst), "l"(src));
}
__device__ __forceinline__ void cp_commit() {
    asm volatile("cp.async.commit_group;" ::: "memory");
}
__device__ __forceinline__ void cp_wait1() {
    asm volatile("cp.async.wait_group 1;" ::: "memory");
}

// ---------------- activation helpers ----------------
__device__ __forceinline__ float fsig(float x) {
    return __fdividef(1.0f, 1.0f + __expf(-x));
}
__device__ __forceinline__ float ftanh(float x) {
    x = fminf(x, 15.0f);
    float e = __expf(2.0f * x);
    return __fdividef(e - 1.0f, e + 1.0f);
}

// ---------------- fp32 -> bf16 hi/lo split (with K zero-padding) ----------
__global__ void convert_split(const float* __restrict__ src,
                              __nv_bfloat16* __restrict__ dhi,
                              __nv_bfloat16* __restrict__ dlo,
                              unsigned rows, unsigned Ksrc, unsigned Kpad)
{
    unsigned total = rows * Kpad;
    for (unsigned idx = blockIdx.x * blockDim.x + threadIdx.x; idx < total;
         idx += gridDim.x * blockDim.x) {
        unsigned row = idx / Kpad;
        unsigned k = idx - row * Kpad;
        float v = (k < Ksrc) ? src[(size_t)row * Ksrc + k] : 0.0f;
        __nv_bfloat16 h = __float2bfloat16_rn(v);
        dhi[idx] = h;
        dlo[idx] = __float2bfloat16_rn(v - __bfloat162float(h));
    }
}

// ---------------- split-bf16 GEMM via mma.sync (HMMA) --------------------
#define PIT 72
#define PITB 144
__global__ __launch_bounds__(256) void gemm_mma(
    const __nv_bfloat16* __restrict__ a_hi, const __nv_bfloat16* __restrict__ a_lo,
    const __nv_bfloat16* __restrict__ w_hi, const __nv_bfloat16* __restrict__ w_lo,
    int Kpad, int nchunks,
    const float* __restrict__ b1, const float* __restrict__ b2,
    float* __restrict__ C)
{
    extern __shared__ __nv_bfloat16 sm[];
    __nv_bfloat16* sAh = sm;
    __nv_bfloat16* sAl = sm + 128 * PIT;
    __nv_bfloat16* sBh = sm + 2 * 128 * PIT;
    __nv_bfloat16* sBl = sm + 3 * 128 * PIT;
    float* sbias = (float*)(sm + 4 * 128 * PIT);

    const int tid  = threadIdx.x;
    const int wid  = tid >> 5;
    const int lane = tid & 31;
    const int wm   = wid & 3;
    const int wn   = wid >> 2;
    const int m0   = blockIdx.x * 128;
    const int n0   = blockIdx.y * 128;

    if (tid < 128) sbias[tid] = b1[n0 + tid] + b2[n0 + tid];

    const uint32_t sbAh = smem_u32(sAh), sbAl = smem_u32(sAl);
    const uint32_t sbBh = smem_u32(sBh), sbBl = smem_u32(sBl);

    const uint32_t aoff = (uint32_t)(lane & 15) * PITB + (uint32_t)(lane >> 4) * 16;
    const uint32_t boff = ((uint32_t)((lane & 7) + ((lane >> 4) << 3))) * PITB
                        + (uint32_t)((lane >> 3) & 1) * 16;

    float acc[2][8][4];
#pragma unroll
    for (int mt = 0; mt < 2; mt++)
#pragma unroll
        for (int nt = 0; nt < 8; nt++)
#pragma unroll
            for (int q = 0; q < 4; q++) acc[mt][nt][q] = 0.0f;

    for (int c = 0; c < nchunks; c++) {
        const int kb = c * 64;
#pragma unroll
        for (int i = 0; i < 4; i++) {
            int idx = tid + i * 256;
            int row = idx >> 3, f4 = idx & 7;
            *(float4*)&sAh[row * PIT + f4 * 8] =
                *(const float4*)(a_hi + (size_t)(m0 + row) * Kpad + kb + f4 * 8);
            *(float4*)&sAl[row * PIT + f4 * 8] =
                *(const float4*)(a_lo + (size_t)(m0 + row) * Kpad + kb + f4 * 8);
            *(float4*)&sBh[row * PIT + f4 * 8] =
                *(const float4*)(w_hi + (size_t)(n0 + row) * Kpad + kb + f4 * 8);
            *(float4*)&sBl[row * PIT + f4 * 8] =
                *(const float4*)(w_lo + (size_t)(n0 + row) * Kpad + kb + f4 * 8);
        }
        __syncthreads();

#pragma unroll
        for (int ks = 0; ks < 4; ks++) {
            const uint32_t kbyte = (uint32_t)(ks * 32);

            uint32_t ah[2][4], al[2][4];
#pragma unroll
            for (int mt = 0; mt < 2; mt++) {
                uint32_t rbase = (uint32_t)(wm * 32 + mt * 16) * PITB + aoff + kbyte;
                ldm_x4(ah[mt][0], ah[mt][1], ah[mt][2], ah[mt][3], sbAh + rbase);
                ldm_x4(al[mt][0], al[mt][1], al[mt][2], al[mt][3], sbAl + rbase);
            }

#pragma unroll
            for (int half = 0; half < 2; half++) {
                uint32_t bh[4][2], bl[4][2];
#pragma unroll
                for (int p = 0; p < 2; p++) {
                    uint32_t nb = (uint32_t)(wn * 64 + half * 32 + p * 16) * PITB + boff + kbyte;
                    ldm_x4(bh[2*p][0], bh[2*p][1], bh[2*p+1][0], bh[2*p+1][1], sbBh + nb);
                    ldm_x4(bl[2*p][0], bl[2*p][1], bl[2*p+1][0], bl[2*p+1][1], sbBl + nb);
                }
#pragma unroll
                for (int mt = 0; mt < 2; mt++)
#pragma unroll
                    for (int nt = 0; nt < 4; nt++) {
                        float* cc = acc[mt][half * 4 + nt];
                        mma_bf16(cc, ah[mt], bh[nt]);
                        mma_bf16(cc, ah[mt], bl[nt]);
                        mma_bf16(cc, al[mt], bh[nt]);
                    }
            }
        }
        __syncthreads();
    }

    const int g = lane >> 2, t = lane & 3;
#pragma unroll
    for (int mt = 0; mt < 2; mt++) {
        const int row0 = m0 + wm * 32 + mt * 16 + g;
#pragma unroll
        for (int nt = 0; nt < 8; nt++) {
            const int cl = wn * 64 + nt * 8 + 2 * t;
            float2 v0, v1;
            v0.x = acc[mt][nt][0] + sbias[cl];
            v0.y = acc[mt][nt][1] + sbias[cl + 1];
            v1.x = acc[mt][nt][2] + sbias[cl];
            v1.y = acc[mt][nt][3] + sbias[cl + 1];
            *(float2*)&C[(size_t)row0 * GG + n0 + cl] = v0;
            *(float2*)&C[(size_t)(row0 + 8) * GG + n0 + cl] = v1;
        }
    }
}

// ---------------- tensorized bidirectional LSTM recurrence ----------------
// 64 batch rows/CTA, 1 direction. 8 warps = 2(M half of 32) x 4(col group of 32).
// Each warp owns the SAME 32 hidden cols in all 4 gates -> local activations.
// W_hh hi/lo streamed gate-quarter at a time via cp.async double buffer.
#define HPITB 272            // smem row pitch bytes (136 bf16) -> conflict-free ldmatrix
#define WCHUNKB 34816        // one gate-quarter chunk (128 rows x 272B)
#define RECSMEM (4 * WCHUNKB + 2 * 64 * HPITB)   // 139264 + 34816 = 174080
__global__ __launch_bounds__(256, 1) void lstm_rec_mma(
    const float* __restrict__ xp_f, const float* __restrict__ xp_b,
    const __nv_bfloat16* __restrict__ whh_hi_base,   // 2 dirs, each [512][128]
    const __nv_bfloat16* __restrict__ whh_lo_base,
    float* __restrict__ out32,
    __nv_bfloat16* __restrict__ ohi, __nv_bfloat16* __restrict__ olo)
{
    extern __shared__ __nv_bfloat16 smr[];
    const uint32_t sb = smem_u32(smr);
    const uint32_t hHi = sb + 4 * WCHUNKB;
    const uint32_t hLo = hHi + 64 * HPITB;

    const int dir = blockIdx.y;
    const float* xp = dir ? xp_b : xp_f;
    const __nv_bfloat16* whh_hi = whh_hi_base + (size_t)dir * GG * HH;
    const __nv_bfloat16* whh_lo = whh_lo_base + (size_t)dir * GG * HH;

    const int tid  = threadIdx.x;
    const int wid  = tid >> 5;
    const int lane = tid & 31;
    const int wm   = wid & 1;        // M half (32 rows)
    const int wn   = wid >> 1;       // 0..3 -> hidden col group of 32
    const int b0   = blockIdx.x * 64;
    const int g4   = lane >> 2;
    const int t4   = lane & 3;

    const uint32_t aoff = (uint32_t)(lane & 15) * HPITB + (uint32_t)(lane >> 4) * 16;
    const uint32_t boff = ((uint32_t)((lane & 7) + ((lane >> 4) << 3))) * HPITB
                        + (uint32_t)((lane >> 3) & 1) * 16;

    // zero h (hi+lo regions, contiguous 2*64*272 bytes)
    for (int i = tid; i < (2 * 64 * HPITB) / 4; i += 256)
        *(uint32_t*)((char*)smr + 4 * WCHUNKB + i * 4) = 0u;
    __syncthreads();

    // prefetch W chunk q into buffer (q&1): gate = q&3
    auto prefetch = [&](int q) {
        if (q < 40) {
            const int gate = q & 3;
            const uint32_t dhB = sb + (uint32_t)((q & 1) * 2) * WCHUNKB;
            const __nv_bfloat16* ghi = whh_hi + (size_t)gate * 128 * HH;
            const __nv_bfloat16* glo = whh_lo + (size_t)gate * 128 * HH;
#pragma unroll
            for (int i = 0; i < 8; i++) {
                int idx = tid + i * 256;       // 0..2047
                int row = idx >> 4, seg = idx & 15;
                cp16(dhB + row * HPITB + seg * 16, ghi + row * HH + seg * 8);
                cp16(dhB + WCHUNKB + row * HPITB + seg * 16, glo + row * HH + seg * 8);
            }
        }
        cp_commit();
    };

    float cst[2][4][4];
#pragma unroll
    for (int mt = 0; mt < 2; mt++)
#pragma unroll
        for (int nt = 0; nt < 4; nt++)
#pragma unroll
            for (int e = 0; e < 4; e++) cst[mt][nt][e] = 0.0f;

    prefetch(0);

    float acc[4][2][4][4];

    for (int s = 0; s < TT; s++) {
        const int t = dir ? (TT - 1 - s) : s;

        // init accumulators from xproj (biases pre-folded by GEMM epilogue)
#pragma unroll
        for (int gate = 0; gate < 4; gate++)
#pragma unroll
            for (int mt = 0; mt < 2; mt++) {
                const int r = wm * 32 + mt * 16 + g4;
                const size_t base0 = ((size_t)(b0 + r) * TT + t) * GG + gate * 128;
                const size_t base1 = ((size_t)(b0 + r + 8) * TT + t) * GG + gate * 128;
#pragma unroll
                for (int nt = 0; nt < 4; nt++) {
                    const int j = wn * 32 + nt * 8 + 2 * t4;
                    float2 v0 = *(const float2*)&xp[base0 + j];
                    float2 v1 = *(const float2*)&xp[base1 + j];
                    acc[gate][mt][nt][0] = v0.x; acc[gate][mt][nt][1] = v0.y;
                    acc[gate][mt][nt][2] = v1.x; acc[gate][mt][nt][3] = v1.y;
                }
            }

        // gates += h_prev @ W_hh^T  (3-term split-bf16)
#pragma unroll
        for (int gate = 0; gate < 4; gate++) {
            const int q = s * 4 + gate;
            prefetch(q + 1);
            cp_wait1();
            __syncthreads();

            const uint32_t wbH = sb + (uint32_t)((q & 1) * 2) * WCHUNKB;
            const uint32_t wbL = wbH + WCHUNKB;

#pragma unroll
            for (int ks = 0; ks < 8; ks++) {
                const uint32_t kb = (uint32_t)(ks * 32);
                uint32_t ah[2][4], al[2][4];
#pragma unroll
                for (int mt = 0; mt < 2; mt++) {
                    uint32_t rb = (uint32_t)(wm * 32 + mt * 16) * HPITB + aoff + kb;
                    ldm_x4(ah[mt][0], ah[mt][1], ah[mt][2], ah[mt][3], hHi + rb);
                    ldm_x4(al[mt][0], al[mt][1], al[mt][2], al[mt][3], hLo + rb);
                }
                uint32_t bh[4][2], bl[4][2];
#pragma unroll
                for (int p = 0; p < 2; p++) {
                    uint32_t nb = (uint32_t)(wn * 32 + p * 16) * HPITB + boff + kb;
                    ldm_x4(bh[2*p][0], bh[2*p][1], bh[2*p+1][0], bh[2*p+1][1], wbH + nb);
                    ldm_x4(bl[2*p][0], bl[2*p][1], bl[2*p+1][0], bl[2*p+1][1], wbL + nb);
                }
#pragma unroll
                for (int mt = 0; mt < 2; mt++)
#pragma unroll
                    for (int nt = 0; nt < 4; nt++) {
                        float* cc = acc[gate][mt][nt];
                        mma_bf16(cc, ah[mt], bh[nt]);
                        mma_bf16(cc, ah[mt], bl[nt]);
                        mma_bf16(cc, al[mt], bh[nt]);
                    }
            }
            __syncthreads();
        }

        // activations + cell update + h emit
#pragma unroll
        for (int mt = 0; mt < 2; mt++) {
            const int r = wm * 32 + mt * 16 + g4;
#pragma unroll
            for (int nt = 0; nt < 4; nt++) {
                const int j = wn * 32 + nt * 8 + 2 * t4;
                float hv[4];
#pragma unroll
                for (int e = 0; e < 4; e++) {
                    float ig = fsig(acc[0][mt][nt][e]);
                    float fg = fsig(acc[1][mt][nt][e]);
                    float gg = ftanh(acc[2][mt][nt][e]);
                    float og = fsig(acc[3][mt][nt][e]);
                    float cc = fg * cst[mt][nt][e] + ig * gg;
                    cst[mt][nt][e] = cc;
                    hv[e] = og * ftanh(cc);
                }
                // pack hi/lo bf16 pairs
                __nv_bfloat16 h0x = __float2bfloat16_rn(hv[0]);
                __nv_bfloat16 h0y = __float2bfloat16_rn(hv[1]);
                __nv_bfloat16 h1x = __float2bfloat16_rn(hv[2]);
                __nv_bfloat16 h1y = __float2bfloat16_rn(hv[3]);
                __nv_bfloat162 hp0; hp0.x = h0x; hp0.y = h0y;
                __nv_bfloat162 hp1; hp1.x = h1x; hp1.y = h1y;
                __nv_bfloat162 lp0, lp1;
                lp0.x = __float2bfloat16_rn(hv[0] - __bfloat162float(h0x));
                lp0.y = __float2bfloat16_rn(hv[1] - __bfloat162float(h0y));
                lp1.x = __float2bfloat16_rn(hv[2] - __bfloat162float(h1x));
                lp1.y = __float2bfloat16_rn(hv[3] - __bfloat162float(h1y));
                uint32_t uh0 = *reinterpret_cast<uint32_t*>(&hp0);
                uint32_t uh1 = *reinterpret_cast<uint32_t*>(&hp1);
                uint32_t ul0 = *reinterpret_cast<uint32_t*>(&lp0);
                uint32_t ul1 = *reinterpret_cast<uint32_t*>(&lp1);

                // smem h for next step
                *(uint32_t*)((char*)smr + (hHi - sb) + r * HPITB + j * 2) = uh0;
                *(uint32_t*)((char*)smr + (hHi - sb) + (r + 8) * HPITB + j * 2) = uh1;
                *(uint32_t*)((char*)smr + (hLo - sb) + r * HPITB + j * 2) = ul0;
                *(uint32_t*)((char*)smr + (hLo - sb) + (r + 8) * HPITB + j * 2) = ul1;

                // gmem output
                const size_t ob0 = ((size_t)(b0 + r) * TT + t) * (2 * HH) + dir * HH + j;
                const size_t ob1 = ((size_t)(b0 + r + 8) * TT + t) * (2 * HH) + dir * HH + j;
                if (out32) {
                    *(float2*)&out32[ob0] = make_float2(hv[0], hv[1]);
                    *(float2*)&out32[ob1] = make_float2(hv[2], hv[3]);
                } else {
                    *(uint32_t*)&ohi[ob0] = uh0;
                    *(uint32_t*)&ohi[ob1] = uh1;
                    *(uint32_t*)&olo[ob0] = ul0;
                    *(uint32_t*)&olo[ob1] = ul1;
                }
            }
        }
        // next iteration's first cp_wait1+__syncthreads publishes these h writes
    }
}

// ---------------- fused maxpool(T) + FC(512->64) + ReLU + FC(64->1) -------
#define W1PITCH 517
__global__ __launch_bounds__(256) void pool_fc(
    const float* __restrict__ o2,
    const float* __restrict__ fc1w, const float* __restrict__ fc1b,
    const float* __restrict__ fc2w, const float* __restrict__ fc2b,
    float* __restrict__ y, int rows_per_warp)
{
    extern __shared__ float smf[];
    float* w1    = smf;
    float* feats = smf + 64 * W1PITCH;

    for (int i = threadIdx.x; i < 64 * 512; i += 256) {
        int j = i >> 9, f = i & 511;
        w1[j * W1PITCH + f] = fc1w[i];
    }
    __syncthreads();

    const int wid  = threadIdx.x >> 5;
    const int lane = threadIdx.x & 31;
    float* myfeat = feats + wid * 512;

    for (int it = 0; it < rows_per_warp; it++) {
        int b = blockIdx.x * (8 * rows_per_warp) + it * 8 + wid;

#pragma unroll
        for (int q = 0; q < 8; q++) {
            int cc = lane + q * 32;
            float m0 = -3.4e38f, m1 = -3.4e38f;
#pragma unroll
            for (int t = 0; t < 5; t++)
                m0 = fmaxf(m0, o2[((size_t)b * TT + t) * (2 * HH) + cc]);
#pragma unroll
            for (int t = 5; t < 10; t++)
                m1 = fmaxf(m1, o2[((size_t)b * TT + t) * (2 * HH) + cc]);
            myfeat[cc * 2 + 0] = m0;
            myfeat[cc * 2 + 1] = m1;
        }
        __syncwarp();

        float a0 = fc1b[lane];
        float a1 = fc1b[lane + 32];
        const float* wr0 = &w1[lane * W1PITCH];
        const float* wr1 = &w1[(lane + 32) * W1PITCH];
#pragma unroll 8
        for (int f = 0; f < 512; f++) {
            float v = myfeat[f];
            a0 += v * wr0[f];
            a1 += v * wr1[f];
        }
        a0 = fmaxf(a0, 0.0f);
        a1 = fmaxf(a1, 0.0f);

        float p = a0 * fc2w[lane] + a1 * fc2w[lane + 32];
#pragma unroll
        for (int off = 16; off; off >>= 1)
            p += __shfl_down_sync(0xffffffffu, p, off);
        if (lane == 0) y[b] = p + fc2b[0];
        __syncwarp();
    }
}

// ---------------- launch ----------------
extern "C" void kernel_launch(void* const* d_in, const int* in_sizes, int n_in,
                              void* d_out, int out_size)
{
    const float* x       = (const float*)d_in[0];
    const float* w_ih1_f = (const float*)d_in[1];
    const float* w_hh1_f = (const float*)d_in[2];
    const float* b_ih1_f = (const float*)d_in[3];
    const float* b_hh1_f = (const float*)d_in[4];
    const float* w_ih1_b = (const float*)d_in[5];
    const float* w_hh1_b = (const float*)d_in[6];
    const float* b_ih1_b = (const float*)d_in[7];
    const float* b_hh1_b = (const float*)d_in[8];
    const float* w_ih2_f = (const float*)d_in[9];
    const float* w_hh2_f = (const float*)d_in[10];
    const float* b_ih2_f = (const float*)d_in[11];
    const float* b_hh2_f = (const float*)d_in[12];
    const float* w_ih2_b = (const float*)d_in[13];
    const float* w_hh2_b = (const float*)d_in[14];
    const float* b_ih2_b = (const float*)d_in[15];
    const float* b_hh2_b = (const float*)d_in[16];
    const float* fc1_w   = (const float*)d_in[17];
    const float* fc1_b   = (const float*)d_in[18];
    const float* fc2_w   = (const float*)d_in[19];
    const float* fc2_b   = (const float*)d_in[20];
    float* y = (float*)d_out;

    float *xpf, *xpb, *o2;
    __nv_bfloat16 *xhi, *xlo, *ohi, *olo, *whi, *wlo, *whhhi, *whhlo;
    cudaGetSymbolAddress((void**)&xpf, g_xpf);
    cudaGetSymbolAddress((void**)&xpb, g_xpb);
    cudaGetSymbolAddress((void**)&o2,  g_o2);
    cudaGetSymbolAddress((void**)&xhi, g_xhi);
    cudaGetSymbolAddress((void**)&xlo, g_xlo);
    cudaGetSymbolAddress((void**)&ohi, g_ohi);
    cudaGetSymbolAddress((void**)&olo, g_olo);
    cudaGetSymbolAddress((void**)&whi, g_whi);
    cudaGetSymbolAddress((void**)&wlo, g_wlo);
    cudaGetSymbolAddress((void**)&whhhi, g_whhhi);
    cudaGetSymbolAddress((void**)&whhlo, g_whhlo);

    const int poolSmem = (64 * W1PITCH + 8 * 512) * 4;
    const int gemmSmem = 4 * 128 * PIT * 2 + 128 * 4;
    cudaFuncSetAttribute(pool_fc,  cudaFuncAttributeMaxDynamicSharedMemorySize, poolSmem);
    cudaFuncSetAttribute(gemm_mma, cudaFuncAttributeMaxDynamicSharedMemorySize, gemmSmem);
    cudaFuncSetAttribute(lstm_rec_mma, cudaFuncAttributeMaxDynamicSharedMemorySize, RECSMEM);

    const size_t WSLOT = (size_t)GG * K2P;
    const size_t HSLOT = (size_t)GG * HH;
    dim3 gemmGrid(MM / 128, GG / 128);
    dim3 recGrid(BB / 64, 2);

    // 0) x split
    convert_split<<<16384, 256>>>(x, xhi, xlo, MM, II, K1P);
    // 1-4) layer-1 weight splits (w_ih + w_hh)
    convert_split<<<512, 256>>>(w_ih1_f, whi + 0 * WSLOT, wlo + 0 * WSLOT, GG, II, K1P);
    convert_split<<<512, 256>>>(w_ih1_b, whi + 1 * WSLOT, wlo + 1 * WSLOT, GG, II, K1P);
    convert_split<<<256, 256>>>(w_hh1_f, whhhi + 0 * HSLOT, whhlo + 0 * HSLOT, GG, HH, HH);
    convert_split<<<256, 256>>>(w_hh1_b, whhhi + 1 * HSLOT, whhlo + 1 * HSLOT, GG, HH, HH);

    // 5-6) layer 1 xproj (HMMA) — launch #5 is the ncu capture target
    gemm_mma<<<gemmGrid, 256, gemmSmem>>>(xhi, xlo, whi + 0 * WSLOT, wlo + 0 * WSLOT,
                                          K1P, 3, b_ih1_f, b_hh1_f, xpf);
    gemm_mma<<<gemmGrid, 256, gemmSmem>>>(xhi, xlo, whi + 1 * WSLOT, wlo + 1 * WSLOT,
                                          K1P, 3, b_ih1_b, b_hh1_b, xpb);

    // 7-10) layer-2 weight splits
    convert_split<<<512, 256>>>(w_ih2_f, whi + 2 * WSLOT, wlo + 2 * WSLOT, GG, 2 * HH, K2P);
    convert_split<<<512, 256>>>(w_ih2_b, whi + 3 * WSLOT, wlo + 3 * WSLOT, GG, 2 * HH, K2P);
    convert_split<<<256, 256>>>(w_hh2_f, whhhi + 2 * HSLOT, whhlo + 2 * HSLOT, GG, HH, HH);
    convert_split<<<256, 256>>>(w_hh2_b, whhhi + 3 * HSLOT, whhlo + 3 * HSLOT, GG, HH, HH);

    // 11) layer 1 recurrence (tensorized) -> bf16 hi/lo for layer-2 GEMM A
    lstm_rec_mma<<<recGrid, 256, RECSMEM>>>(xpf, xpb, whhhi, whhlo,
                                            (float*)nullptr, ohi, olo);

    // 12-13) layer 2 xproj (K=256)
    gemm_mma<<<gemmGrid, 256, gemmSmem>>>(ohi, olo, whi + 2 * WSLOT, wlo + 2 * WSLOT,
                                          K2P, 4, b_ih2_f, b_hh2_f, xpf);
    gemm_mma<<<gemmGrid, 256, gemmSmem>>>(ohi, olo, whi + 3 * WSLOT, wlo + 3 * WSLOT,
                                          K2P, 4, b_ih2_b, b_hh2_b, xpb);

    // 14) layer 2 recurrence -> fp32 output
    lstm_rec_mma<<<recGrid, 256, RECSMEM>>>(xpf, xpb, whhhi + 2 * HSLOT, whhlo + 2 * HSLOT,
                                            o2, (__nv_bfloat16*)nullptr, (__nv_bfloat16*)nullptr);

    // 15) pool + FC head
    pool_fc<<<256, 256, poolSmem>>>(o2, fc1_w, fc1_b, fc2_w, fc2_b, y, 8);
}

// round 5
// speedup vs baseline: 2.3916x; 1.2723x over previous
#include <cuda_runtime.h>
#include <cuda_fp16.h>
#include <cstdint>

// Problem constants
#define BB 16384
#define TT 10
#define II 184
#define HH 128
#define GG 512            // 4*H
#define MM (BB*TT)        // 163840 rows for xproj GEMMs
#define K1P 192           // layer-1 K padded (184 -> 192)
#define K2P 256           // layer-2 K

// ---------------- device scratch (no allocations allowed) ----------------
__device__ float g_xpf[(size_t)MM * GG];
__device__ float g_xpb[(size_t)MM * GG];
__device__ float g_o2 [(size_t)MM * 2 * HH];
__device__ __half g_xhi[(size_t)MM * K1P];          // x split hi (fp16)
__device__ __half g_xlo[(size_t)MM * K1P];          // x split lo
__device__ __half g_ohi[(size_t)MM * K2P];          // layer1 out split hi
__device__ __half g_olo[(size_t)MM * K2P];          // layer1 out split lo
__device__ __half g_whi[4 * (size_t)GG * K2P];      // w_ih hi only (4 slots)
__device__ __half g_whhhi[4 * (size_t)GG * HH];     // w_hh hi only (4 slots)

// ---------------- small PTX helpers ----------------
__device__ __forceinline__ uint32_t smem_u32(const void* p) {
    uint32_t a;
    asm("{ .reg .u64 t; cvta.to.shared.u64 t, %1; cvt.u32.u64 %0, t; }" : "=r"(a) : "l"(p));
    return a;
}
__device__ __forceinline__ void ldm_x4(uint32_t& r0, uint32_t& r1, uint32_t& r2, uint32_t& r3,
                                       uint32_t addr) {
    asm volatile("ldmatrix.sync.aligned.m8n8.x4.shared.b16 {%0,%1,%2,%3}, [%4];"
                 : "=r"(r0), "=r"(r1), "=r"(r2), "=r"(r3) : "r"(addr));
}
__device__ __forceinline__ void mma_f16(float* c, const uint32_t* a, const uint32_t* b) {
    asm volatile(
        "mma.sync.aligned.m16n8k16.row.col.f32.f16.f16.f32 "
        "{%0,%1,%2,%3}, {%4,%5,%6,%7}, {%8,%9}, {%0,%1,%2,%3};"
        : "+f"(c[0]), "+f"(c[1]), "+f"(c[2]), "+f"(c[3])
        : "r"(a[0]), "r"(a[1]), "r"(a[2]), "r"(a[3]), "r"(b[0]), "r"(b[1]));
}
__device__ __forceinline__ void cp16(uint32_t dst, const void* src) {
    asm volatile("cp.async.cg.shared.global [%0], [%1], 16;" :: "r"(dst), "l"(src));
}
__device__ __forceinline__ void cp_commit() {
    asm volatile("cp.async.commit_group;" ::: "memory");
}
__device__ __forceinline__ void cp_wait1() {
    asm volatile("cp.async.wait_group 1;" ::: "memory");
}

// ---------------- activation helpers ----------------
__device__ __forceinline__ float fsig(float x) {
    return __fdividef(1.0f, 1.0f + __expf(-x));
}
__device__ __forceinline__ float ftanh(float x) {
    x = fminf(x, 15.0f);
    float e = __expf(2.0f * x);
    return __fdividef(e - 1.0f, e + 1.0f);
}

// ---------------- fp32 -> fp16 hi/lo split (with K zero-padding) ----------
__global__ void convert_split(const float* __restrict__ src,
                              __half* __restrict__ dhi,
                              __half* __restrict__ dlo,
                              unsigned rows, unsigned Ksrc, unsigned Kpad)
{
    unsigned total = rows * Kpad;
    for (unsigned idx = blockIdx.x * blockDim.x + threadIdx.x; idx < total;
         idx += gridDim.x * blockDim.x) {
        unsigned row = idx / Kpad;
        unsigned k = idx - row * Kpad;
        float v = (k < Ksrc) ? src[(size_t)row * Ksrc + k] : 0.0f;
        __half h = __float2half_rn(v);
        dhi[idx] = h;
        dlo[idx] = __float2half_rn(v - __half2float(h));
    }
}

// ---------------- fp32 -> fp16 hi only (weights) --------------------------
__global__ void convert_h(const float* __restrict__ src,
                          __half* __restrict__ dhi,
                          unsigned rows, unsigned Ksrc, unsigned Kpad)
{
    unsigned total = rows * Kpad;
    for (unsigned idx = blockIdx.x * blockDim.x + threadIdx.x; idx < total;
         idx += gridDim.x * blockDim.x) {
        unsigned row = idx / Kpad;
        unsigned k = idx - row * Kpad;
        float v = (k < Ksrc) ? src[(size_t)row * Ksrc + k] : 0.0f;
        dhi[idx] = __float2half_rn(v);
    }
}

// ---------------- split-fp16 2-term GEMM via mma.sync (HMMA) --------------
// C[M,512] = (Ahi+Alo)[M,K] @ Whi[512,K]^T + (b1+b2).
#define PIT 72
#define PITB 144
__global__ __launch_bounds__(256) void gemm_mma(
    const __half* __restrict__ a_hi, const __half* __restrict__ a_lo,
    const __half* __restrict__ w_hi,
    int Kpad, int nchunks,
    const float* __restrict__ b1, const float* __restrict__ b2,
    float* __restrict__ C)
{
    extern __shared__ __half sm[];
    __half* sAh = sm;
    __half* sAl = sm + 128 * PIT;
    __half* sBh = sm + 2 * 128 * PIT;
    float* sbias = (float*)(sm + 3 * 128 * PIT);

    const int tid  = threadIdx.x;
    const int wid  = tid >> 5;
    const int lane = tid & 31;
    const int wm   = wid & 3;
    const int wn   = wid >> 2;
    const int m0   = blockIdx.x * 128;
    const int n0   = blockIdx.y * 128;

    if (tid < 128) sbias[tid] = b1[n0 + tid] + b2[n0 + tid];

    const uint32_t sbAh = smem_u32(sAh), sbAl = smem_u32(sAl);
    const uint32_t sbBh = smem_u32(sBh);

    const uint32_t aoff = (uint32_t)(lane & 15) * PITB + (uint32_t)(lane >> 4) * 16;
    const uint32_t boff = ((uint32_t)((lane & 7) + ((lane >> 4) << 3))) * PITB
                        + (uint32_t)((lane >> 3) & 1) * 16;

    float acc[2][8][4];
#pragma unroll
    for (int mt = 0; mt < 2; mt++)
#pragma unroll
        for (int nt = 0; nt < 8; nt++)
#pragma unroll
            for (int q = 0; q < 4; q++) acc[mt][nt][q] = 0.0f;

    for (int c = 0; c < nchunks; c++) {
        const int kb = c * 64;
#pragma unroll
        for (int i = 0; i < 4; i++) {
            int idx = tid + i * 256;
            int row = idx >> 3, f4 = idx & 7;
            *(float4*)&sAh[row * PIT + f4 * 8] =
                *(const float4*)(a_hi + (size_t)(m0 + row) * Kpad + kb + f4 * 8);
            *(float4*)&sAl[row * PIT + f4 * 8] =
                *(const float4*)(a_lo + (size_t)(m0 + row) * Kpad + kb + f4 * 8);
            *(float4*)&sBh[row * PIT + f4 * 8] =
                *(const float4*)(w_hi + (size_t)(n0 + row) * Kpad + kb + f4 * 8);
        }
        __syncthreads();

#pragma unroll
        for (int ks = 0; ks < 4; ks++) {
            const uint32_t kbyte = (uint32_t)(ks * 32);

            uint32_t ah[2][4], al[2][4];
#pragma unroll
            for (int mt = 0; mt < 2; mt++) {
                uint32_t rbase = (uint32_t)(wm * 32 + mt * 16) * PITB + aoff + kbyte;
                ldm_x4(ah[mt][0], ah[mt][1], ah[mt][2], ah[mt][3], sbAh + rbase);
                ldm_x4(al[mt][0], al[mt][1], al[mt][2], al[mt][3], sbAl + rbase);
            }

#pragma unroll
            for (int half = 0; half < 2; half++) {
                uint32_t bh[4][2];
#pragma unroll
                for (int p = 0; p < 2; p++) {
                    uint32_t nb = (uint32_t)(wn * 64 + half * 32 + p * 16) * PITB + boff + kbyte;
                    ldm_x4(bh[2*p][0], bh[2*p][1], bh[2*p+1][0], bh[2*p+1][1], sbBh + nb);
                }
#pragma unroll
                for (int mt = 0; mt < 2; mt++)
#pragma unroll
                    for (int nt = 0; nt < 4; nt++) {
                        float* cc = acc[mt][half * 4 + nt];
                        mma_f16(cc, ah[mt], bh[nt]);   // hi * Whi
                        mma_f16(cc, al[mt], bh[nt]);   // lo * Whi
                    }
            }
        }
        __syncthreads();
    }

    const int g = lane >> 2, t = lane & 3;
#pragma unroll
    for (int mt = 0; mt < 2; mt++) {
        const int row0 = m0 + wm * 32 + mt * 16 + g;
#pragma unroll
        for (int nt = 0; nt < 8; nt++) {
            const int cl = wn * 64 + nt * 8 + 2 * t;
            float2 v0, v1;
            v0.x = acc[mt][nt][0] + sbias[cl];
            v0.y = acc[mt][nt][1] + sbias[cl + 1];
            v1.x = acc[mt][nt][2] + sbias[cl];
            v1.y = acc[mt][nt][3] + sbias[cl + 1];
            *(float2*)&C[(size_t)row0 * GG + n0 + cl] = v0;
            *(float2*)&C[(size_t)(row0 + 8) * GG + n0 + cl] = v1;
        }
    }
}

// ---------------- tensorized bidirectional LSTM recurrence ----------------
// 64 batch rows/CTA, 1 direction. h = hi+lo fp16 in smem; W_hh hi-only fp16
// streamed gate-quarter at a time via cp.async double buffer.
#define HPITB 272            // smem row pitch bytes (136 halves)
#define WCHUNKB 34816        // one gate-quarter (128 rows x 272B), hi only
#define RECSMEM (2 * WCHUNKB + 2 * 64 * HPITB)   // 69632 + 34816 = 104448
__global__ __launch_bounds__(256, 1) void lstm_rec_mma(
    const float* __restrict__ xp_f, const float* __restrict__ xp_b,
    const __half* __restrict__ whh_hi_base,   // 2 dirs, each [512][128]
    float* __restrict__ out32,
    __half* __restrict__ ohi, __half* __restrict__ olo)
{
    extern __shared__ __half smr[];
    const uint32_t sb = smem_u32(smr);
    const uint32_t hHi = sb + 2 * WCHUNKB;
    const uint32_t hLo = hHi + 64 * HPITB;

    const int dir = blockIdx.y;
    const float* xp = dir ? xp_b : xp_f;
    const __half* whh_hi = whh_hi_base + (size_t)dir * GG * HH;

    const int tid  = threadIdx.x;
    const int wid  = tid >> 5;
    const int lane = tid & 31;
    const int wm   = wid & 1;        // M half (32 rows)
    const int wn   = wid >> 1;       // 0..3 -> hidden col group of 32
    const int b0   = blockIdx.x * 64;
    const int g4   = lane >> 2;
    const int t4   = lane & 3;

    const uint32_t aoff = (uint32_t)(lane & 15) * HPITB + (uint32_t)(lane >> 4) * 16;
    const uint32_t boff = ((uint32_t)((lane & 7) + ((lane >> 4) << 3))) * HPITB
                        + (uint32_t)((lane >> 3) & 1) * 16;

    // zero h (hi+lo regions, contiguous 2*64*272 bytes)
    for (int i = tid; i < (2 * 64 * HPITB) / 4; i += 256)
        *(uint32_t*)((char*)smr + 2 * WCHUNKB + i * 4) = 0u;
    __syncthreads();

    // prefetch W chunk q (hi only) into buffer (q&1): gate = q&3
    auto prefetch = [&](int q) {
        if (q < 40) {
            const int gate = q & 3;
            const uint32_t dhB = sb + (uint32_t)(q & 1) * WCHUNKB;
            const __half* ghi = whh_hi + (size_t)gate * 128 * HH;
#pragma unroll
            for (int i = 0; i < 8; i++) {
                int idx = tid + i * 256;       // 0..2047
                int row = idx >> 4, seg = idx & 15;
                cp16(dhB + row * HPITB + seg * 16, ghi + row * HH + seg * 8);
            }
        }
        cp_commit();
    };

    float cst[2][4][4];
#pragma unroll
    for (int mt = 0; mt < 2; mt++)
#pragma unroll
        for (int nt = 0; nt < 4; nt++)
#pragma unroll
            for (int e = 0; e < 4; e++) cst[mt][nt][e] = 0.0f;

    prefetch(0);

    float acc[4][2][4][4];

    for (int s = 0; s < TT; s++) {
        const int t = dir ? (TT - 1 - s) : s;

        // init accumulators from xproj (biases pre-folded by GEMM epilogue)
#pragma unroll
        for (int gate = 0; gate < 4; gate++)
#pragma unroll
            for (int mt = 0; mt < 2; mt++) {
                const int r = wm * 32 + mt * 16 + g4;
                const size_t base0 = ((size_t)(b0 + r) * TT + t) * GG + gate * 128;
                const size_t base1 = ((size_t)(b0 + r + 8) * TT + t) * GG + gate * 128;
#pragma unroll
                for (int nt = 0; nt < 4; nt++) {
                    const int j = wn * 32 + nt * 8 + 2 * t4;
                    float2 v0 = *(const float2*)&xp[base0 + j];
                    float2 v1 = *(const float2*)&xp[base1 + j];
                    acc[gate][mt][nt][0] = v0.x; acc[gate][mt][nt][1] = v0.y;
                    acc[gate][mt][nt][2] = v1.x; acc[gate][mt][nt][3] = v1.y;
                }
            }

        // gates += h_prev @ W_hh^T  (2-term split-fp16)
#pragma unroll
        for (int gate = 0; gate < 4; gate++) {
            const int q = s * 4 + gate;
            prefetch(q + 1);
            cp_wait1();
            __syncthreads();

            const uint32_t wbH = sb + (uint32_t)(q & 1) * WCHUNKB;

#pragma unroll
            for (int ks = 0; ks < 8; ks++) {
                const uint32_t kb = (uint32_t)(ks * 32);
                uint32_t ah[2][4], al[2][4];
#pragma unroll
                for (int mt = 0; mt < 2; mt++) {
                    uint32_t rb = (uint32_t)(wm * 32 + mt * 16) * HPITB + aoff + kb;
                    ldm_x4(ah[mt][0], ah[mt][1], ah[mt][2], ah[mt][3], hHi + rb);
                    ldm_x4(al[mt][0], al[mt][1], al[mt][2], al[mt][3], hLo + rb);
                }
                uint32_t bh[4][2];
#pragma unroll
                for (int p = 0; p < 2; p++) {
                    uint32_t nb = (uint32_t)(wn * 32 + p * 16) * HPITB + boff + kb;
                    ldm_x4(bh[2*p][0], bh[2*p][1], bh[2*p+1][0], bh[2*p+1][1], wbH + nb);
                }
#pragma unroll
                for (int mt = 0; mt < 2; mt++)
#pragma unroll
                    for (int nt = 0; nt < 4; nt++) {
                        float* cc = acc[gate][mt][nt];
                        mma_f16(cc, ah[mt], bh[nt]);
                        mma_f16(cc, al[mt], bh[nt]);
                    }
            }
            __syncthreads();
        }

        // activations + cell update + h emit
#pragma unroll
        for (int mt = 0; mt < 2; mt++) {
            const int r = wm * 32 + mt * 16 + g4;
#pragma unroll
            for (int nt = 0; nt < 4; nt++) {
                const int j = wn * 32 + nt * 8 + 2 * t4;
                float hv[4];
#pragma unroll
                for (int e = 0; e < 4; e++) {
                    float ig = fsig(acc[0][mt][nt][e]);
                    float fg = fsig(acc[1][mt][nt][e]);
                    float gg = ftanh(acc[2][mt][nt][e]);
                    float og = fsig(acc[3][mt][nt][e]);
                    float cc = fg * cst[mt][nt][e] + ig * gg;
                    cst[mt][nt][e] = cc;
                    hv[e] = og * ftanh(cc);
                }
                __half h0x = __float2half_rn(hv[0]);
                __half h0y = __float2half_rn(hv[1]);
                __half h1x = __float2half_rn(hv[2]);
                __half h1y = __float2half_rn(hv[3]);
                __half2 hp0 = __halves2half2(h0x, h0y);
                __half2 hp1 = __halves2half2(h1x, h1y);
                __half2 lp0 = __halves2half2(__float2half_rn(hv[0] - __half2float(h0x)),
                                             __float2half_rn(hv[1] - __half2float(h0y)));
                __half2 lp1 = __halves2half2(__float2half_rn(hv[2] - __half2float(h1x)),
                                             __float2half_rn(hv[3] - __half2float(h1y)));
                uint32_t uh0 = *reinterpret_cast<uint32_t*>(&hp0);
                uint32_t uh1 = *reinterpret_cast<uint32_t*>(&hp1);
                uint32_t ul0 = *reinterpret_cast<uint32_t*>(&lp0);
                uint32_t ul1 = *reinterpret_cast<uint32_t*>(&lp1);

                // smem h for next step
                *(uint32_t*)((char*)smr + (hHi - sb) + r * HPITB + j * 2) = uh0;
                *(uint32_t*)((char*)smr + (hHi - sb) + (r + 8) * HPITB + j * 2) = uh1;
                *(uint32_t*)((char*)smr + (hLo - sb) + r * HPITB + j * 2) = ul0;
                *(uint32_t*)((char*)smr + (hLo - sb) + (r + 8) * HPITB + j * 2) = ul1;

                // gmem output
                const size_t ob0 = ((size_t)(b0 + r) * TT + t) * (2 * HH) + dir * HH + j;
                const size_t ob1 = ((size_t)(b0 + r + 8) * TT + t) * (2 * HH) + dir * HH + j;
                if (out32) {
                    *(float2*)&out32[ob0] = make_float2(hv[0], hv[1]);
                    *(float2*)&out32[ob1] = make_float2(hv[2], hv[3]);
                } else {
                    *(uint32_t*)&ohi[ob0] = uh0;
                    *(uint32_t*)&ohi[ob1] = uh1;
                    *(uint32_t*)&olo[ob0] = ul0;
                    *(uint32_t*)&olo[ob1] = ul1;
                }
            }
        }
        // next iteration's first cp_wait1+__syncthreads publishes these h writes
    }
}

// ---------------- fused maxpool(T) + FC(512->64) + ReLU + FC(64->1) -------
#define W1PITCH 517
__global__ __launch_bounds__(256) void pool_fc(
    const float* __restrict__ o2,
    const float* __restrict__ fc1w, const float* __restrict__ fc1b,
    const float* __restrict__ fc2w, const float* __restrict__ fc2b,
    float* __restrict__ y, int rows_per_warp)
{
    extern __shared__ float smf[];
    float* w1    = smf;
    float* feats = smf + 64 * W1PITCH;

    for (int i = threadIdx.x; i < 64 * 512; i += 256) {
        int j = i >> 9, f = i & 511;
        w1[j * W1PITCH + f] = fc1w[i];
    }
    __syncthreads();

    const int wid  = threadIdx.x >> 5;
    const int lane = threadIdx.x & 31;
    float* myfeat = feats + wid * 512;

    for (int it = 0; it < rows_per_warp; it++) {
        int b = blockIdx.x * (8 * rows_per_warp) + it * 8 + wid;

#pragma unroll
        for (int q = 0; q < 8; q++) {
            int cc = lane + q * 32;
            float m0 = -3.4e38f, m1 = -3.4e38f;
#pragma unroll
            for (int t = 0; t < 5; t++)
                m0 = fmaxf(m0, o2[((size_t)b * TT + t) * (2 * HH) + cc]);
#pragma unroll
            for (int t = 5; t < 10; t++)
                m1 = fmaxf(m1, o2[((size_t)b * TT + t) * (2 * HH) + cc]);
            myfeat[cc * 2 + 0] = m0;
            myfeat[cc * 2 + 1] = m1;
        }
        __syncwarp();

        float a0 = fc1b[lane];
        float a1 = fc1b[lane + 32];
        const float* wr0 = &w1[lane * W1PITCH];
        const float* wr1 = &w1[(lane + 32) * W1PITCH];
#pragma unroll 8
        for (int f = 0; f < 512; f++) {
            float v = myfeat[f];
            a0 += v * wr0[f];
            a1 += v * wr1[f];
        }
        a0 = fmaxf(a0, 0.0f);
        a1 = fmaxf(a1, 0.0f);

        float p = a0 * fc2w[lane] + a1 * fc2w[lane + 32];
#pragma unroll
        for (int off = 16; off; off >>= 1)
            p += __shfl_down_sync(0xffffffffu, p, off);
        if (lane == 0) y[b] = p + fc2b[0];
        __syncwarp();
    }
}

// ---------------- launch ----------------
extern "C" void kernel_launch(void* const* d_in, const int* in_sizes, int n_in,
                              void* d_out, int out_size)
{
    const float* x       = (const float*)d_in[0];
    const float* w_ih1_f = (const float*)d_in[1];
    const float* w_hh1_f = (const float*)d_in[2];
    const float* b_ih1_f = (const float*)d_in[3];
    const float* b_hh1_f = (const float*)d_in[4];
    const float* w_ih1_b = (const float*)d_in[5];
    const float* w_hh1_b = (const float*)d_in[6];
    const float* b_ih1_b = (const float*)d_in[7];
    const float* b_hh1_b = (const float*)d_in[8];
    const float* w_ih2_f = (const float*)d_in[9];
    const float* w_hh2_f = (const float*)d_in[10];
    const float* b_ih2_f = (const float*)d_in[11];
    const float* b_hh2_f = (const float*)d_in[12];
    const float* w_ih2_b = (const float*)d_in[13];
    const float* w_hh2_b = (const float*)d_in[14];
    const float* b_ih2_b = (const float*)d_in[15];
    const float* b_hh2_b = (const float*)d_in[16];
    const float* fc1_w   = (const float*)d_in[17];
    const float* fc1_b   = (const float*)d_in[18];
    const float* fc2_w   = (const float*)d_in[19];
    const float* fc2_b   = (const float*)d_in[20];
    float* y = (float*)d_out;

    float *xpf, *xpb, *o2;
    __half *xhi, *xlo, *ohi, *olo, *whi, *whhhi;
    cudaGetSymbolAddress((void**)&xpf, g_xpf);
    cudaGetSymbolAddress((void**)&xpb, g_xpb);
    cudaGetSymbolAddress((void**)&o2,  g_o2);
    cudaGetSymbolAddress((void**)&xhi, g_xhi);
    cudaGetSymbolAddress((void**)&xlo, g_xlo);
    cudaGetSymbolAddress((void**)&ohi, g_ohi);
    cudaGetSymbolAddress((void**)&olo, g_olo);
    cudaGetSymbolAddress((void**)&whi, g_whi);
    cudaGetSymbolAddress((void**)&whhhi, g_whhhi);

    const int poolSmem = (64 * W1PITCH + 8 * 512) * 4;
    const int gemmSmem = 3 * 128 * PIT * 2 + 128 * 4;    // 55808
    cudaFuncSetAttribute(pool_fc,  cudaFuncAttributeMaxDynamicSharedMemorySize, poolSmem);
    cudaFuncSetAttribute(gemm_mma, cudaFuncAttributeMaxDynamicSharedMemorySize, gemmSmem);
    cudaFuncSetAttribute(lstm_rec_mma, cudaFuncAttributeMaxDynamicSharedMemorySize, RECSMEM);

    const size_t WSLOT = (size_t)GG * K2P;
    const size_t HSLOT = (size_t)GG * HH;
    dim3 gemmGrid(MM / 128, GG / 128);
    dim3 recGrid(BB / 64, 2);

    // 0) x split, 1-2) layer-1 w_ih hi
    convert_split<<<16384, 256>>>(x, xhi, xlo, MM, II, K1P);
    convert_h<<<512, 256>>>(w_ih1_f, whi + 0 * WSLOT, GG, II, K1P);
    convert_h<<<512, 256>>>(w_ih1_b, whi + 1 * WSLOT, GG, II, K1P);

    // 3-4) layer 1 xproj — launch index 4 is the ncu capture target
    gemm_mma<<<gemmGrid, 256, gemmSmem>>>(xhi, xlo, whi + 0 * WSLOT,
                                          K1P, 3, b_ih1_f, b_hh1_f, xpf);
    gemm_mma<<<gemmGrid, 256, gemmSmem>>>(xhi, xlo, whi + 1 * WSLOT,
                                          K1P, 3, b_ih1_b, b_hh1_b, xpb);

    // 5-10) remaining weight conversions
    convert_h<<<256, 256>>>(w_hh1_f, whhhi + 0 * HSLOT, GG, HH, HH);
    convert_h<<<256, 256>>>(w_hh1_b, whhhi + 1 * HSLOT, GG, HH, HH);
    convert_h<<<512, 256>>>(w_ih2_f, whi + 2 * WSLOT, GG, 2 * HH, K2P);
    convert_h<<<512, 256>>>(w_ih2_b, whi + 3 * WSLOT, GG, 2 * HH, K2P);
    convert_h<<<256, 256>>>(w_hh2_f, whhhi + 2 * HSLOT, GG, HH, HH);
    convert_h<<<256, 256>>>(w_hh2_b, whhhi + 3 * HSLOT, GG, HH, HH);

    // 11) layer 1 recurrence -> fp16 hi/lo for layer-2 GEMM A
    lstm_rec_mma<<<recGrid, 256, RECSMEM>>>(xpf, xpb, whhhi,
                                            (float*)nullptr, ohi, olo);

    // 12-13) layer 2 xproj (K=256)
    gemm_mma<<<gemmGrid, 256, gemmSmem>>>(ohi, olo, whi + 2 * WSLOT,
                                          K2P, 4, b_ih2_f, b_hh2_f, xpf);
    gemm_mma<<<gemmGrid, 256, gemmSmem>>>(ohi, olo, whi + 3 * WSLOT,
                                          K2P, 4, b_ih2_b, b_hh2_b, xpb);

    // 14) layer 2 recurrence -> fp32 output
    lstm_rec_mma<<<recGrid, 256, RECSMEM>>>(xpf, xpb, whhhi + 2 * HSLOT,
                                            o2, (__half*)nullptr, (__half*)nullptr);

    // 15) pool + FC head
    pool_fc<<<256, 256, poolSmem>>>(o2, fc1_w, fc1_b, fc2_w, fc2_b, y, 8);
}

// round 7
// speedup vs baseline: 3.0846x; 1.2898x over previous
#include <cuda_runtime.h>
#include <cuda_fp16.h>
#include <cstdint>

// Problem constants
#define BB 16384
#define TT 10
#define II 184
#define HH 128
#define GG 512            // 4*H
#define MM (BB*TT)        // 163840 rows for xproj GEMMs
#define K1P 192           // layer-1 K padded (184 -> 192)
#define K2P 256           // layer-2 K

// ---------------- device scratch (no allocations allowed) ----------------
__device__ float g_xpf[(size_t)MM * GG];
__device__ float g_xpb[(size_t)MM * GG];
__device__ float g_o2 [(size_t)MM * 2 * HH];
__device__ __half g_xhi[(size_t)MM * K1P];          // x split hi (fp16)
__device__ __half g_xlo[(size_t)MM * K1P];          // x split lo
__device__ __half g_ohi[(size_t)MM * K2P];          // layer1 out split hi
__device__ __half g_olo[(size_t)MM * K2P];          // layer1 out split lo
__device__ __half g_whi[4 * (size_t)GG * K2P];      // w_ih hi only (4 slots)
__device__ __half g_whhhi[4 * (size_t)GG * HH];     // w_hh hi only (4 slots)

// ---------------- small PTX helpers ----------------
__device__ __forceinline__ uint32_t smem_u32(const void* p) {
    uint32_t a;
    asm("{ .reg .u64 t; cvta.to.shared.u64 t, %1; cvt.u32.u64 %0, t; }" : "=r"(a) : "l"(p));
    return a;
}
__device__ __forceinline__ void ldm_x4(uint32_t& r0, uint32_t& r1, uint32_t& r2, uint32_t& r3,
                                       uint32_t addr) {
    asm volatile("ldmatrix.sync.aligned.m8n8.x4.shared.b16 {%0,%1,%2,%3}, [%4];"
                 : "=r"(r0), "=r"(r1), "=r"(r2), "=r"(r3) : "r"(addr));
}
__device__ __forceinline__ void mma_f16(float* c, const uint32_t* a, const uint32_t* b) {
    asm volatile(
        "mma.sync.aligned.m16n8k16.row.col.f32.f16.f16.f32 "
        "{%0,%1,%2,%3}, {%4,%5,%6,%7}, {%8,%9}, {%0,%1,%2,%3};"
        : "+f"(c[0]), "+f"(c[1]), "+f"(c[2]), "+f"(c[3])
        : "r"(a[0]), "r"(a[1]), "r"(a[2]), "r"(a[3]), "r"(b[0]), "r"(b[1]));
}
__device__ __forceinline__ void cp16(uint32_t dst, const void* src) {
    asm volatile("cp.async.cg.shared.global [%0], [%1], 16;" :: "r"(dst), "l"(src));
}
__device__ __forceinline__ void cp_commit() {
    asm volatile("cp.async.commit_group;" ::: "memory");
}
__device__ __forceinline__ void cp_wait1() {
    asm volatile("cp.async.wait_group 1;" ::: "memory");
}
__device__ __forceinline__ void cp_wait0() {
    asm volatile("cp.async.wait_group 0;" ::: "memory");
}

// ---------------- activation helpers ----------------
__device__ __forceinline__ float fsig(float x) {
    return __fdividef(1.0f, 1.0f + __expf(-x));
}
__device__ __forceinline__ float ftanh(float x) {
    x = fminf(x, 15.0f);
    float e = __expf(2.0f * x);
    return __fdividef(e - 1.0f, e + 1.0f);
}

// ---------------- fp32 -> fp16 hi/lo split (with K zero-padding) ----------
__global__ void convert_split(const float* __restrict__ src,
                              __half* __restrict__ dhi,
                              __half* __restrict__ dlo,
                              unsigned rows, unsigned Ksrc, unsigned Kpad)
{
    unsigned total = rows * Kpad;
    for (unsigned idx = blockIdx.x * blockDim.x + threadIdx.x; idx < total;
         idx += gridDim.x * blockDim.x) {
        unsigned row = idx / Kpad;
        unsigned k = idx - row * Kpad;
        float v = (k < Ksrc) ? src[(size_t)row * Ksrc + k] : 0.0f;
        __half h = __float2half_rn(v);
        dhi[idx] = h;
        dlo[idx] = __float2half_rn(v - __half2float(h));
    }
}

// ---------------- fp32 -> fp16 hi only (weights) --------------------------
__global__ void convert_h(const float* __restrict__ src,
                          __half* __restrict__ dhi,
                          unsigned rows, unsigned Ksrc, unsigned Kpad)
{
    unsigned total = rows * Kpad;
    for (unsigned idx = blockIdx.x * blockDim.x + threadIdx.x; idx < total;
         idx += gridDim.x * blockDim.x) {
        unsigned row = idx / Kpad;
        unsigned k = idx - row * Kpad;
        float v = (k < Ksrc) ? src[(size_t)row * Ksrc + k] : 0.0f;
        dhi[idx] = __float2half_rn(v);
    }
}

// ---------------- split-fp16 2-term GEMM, cp.async 2-stage pipeline -------
// C[M,512] = (Ahi+Alo)[M,K] @ Whi[512,K]^T + (b1+b2).
// grid = (N/128, M/128): N fastest -> A tile L2 reuse across its 4 N-blocks.
#define PIT 72
#define PITB 144
#define ATILEB (128 * PITB)            // 18432 bytes per operand tile
#define GSTAGEB (3 * ATILEB)           // 55296 bytes per pipeline stage
#define GEMMSMEM (2 * GSTAGEB + 512)   // 111104
__global__ __launch_bounds__(256) void gemm_mma(
    const __half* __restrict__ a_hi, const __half* __restrict__ a_lo,
    const __half* __restrict__ w_hi,
    int Kpad, int nchunks,
    const float* __restrict__ b1, const float* __restrict__ b2,
    float* __restrict__ C)
{
    extern __shared__ __half sm[];
    const uint32_t sb0 = smem_u32(sm);
    float* sbias = (float*)((char*)sm + 2 * GSTAGEB);

    const int tid  = threadIdx.x;
    const int wid  = tid >> 5;
    const int lane = tid & 31;
    const int wm   = wid & 3;
    const int wn   = wid >> 2;
    const int n0   = blockIdx.x * 128;   // N fastest
    const int m0   = blockIdx.y * 128;

    if (tid < 128) sbias[tid] = b1[n0 + tid] + b2[n0 + tid];

    const uint32_t aoff = (uint32_t)(lane & 15) * PITB + (uint32_t)(lane >> 4) * 16;
    const uint32_t boff = ((uint32_t)((lane & 7) + ((lane >> 4) << 3))) * PITB
                        + (uint32_t)((lane >> 3) & 1) * 16;

    // issue cp.async for chunk c into stage st (3 tiles: Ahi, Alo, Bhi)
    auto load_chunk = [&](int c, int st) {
        const int kb = c * 64;
        const uint32_t base = sb0 + (uint32_t)st * GSTAGEB;
#pragma unroll
        for (int i = 0; i < 4; i++) {
            int idx = tid + i * 256;          // 0..1023
            int row = idx >> 3, seg = idx & 7;
            uint32_t d = base + (uint32_t)row * PITB + (uint32_t)seg * 16;
            cp16(d,              a_hi + (size_t)(m0 + row) * Kpad + kb + seg * 8);
            cp16(d + ATILEB,     a_lo + (size_t)(m0 + row) * Kpad + kb + seg * 8);
            cp16(d + 2 * ATILEB, w_hi + (size_t)(n0 + row) * Kpad + kb + seg * 8);
        }
        cp_commit();
    };

    float acc[2][8][4];
#pragma unroll
    for (int mt = 0; mt < 2; mt++)
#pragma unroll
        for (int nt = 0; nt < 8; nt++)
#pragma unroll
            for (int q = 0; q < 4; q++) acc[mt][nt][q] = 0.0f;

    load_chunk(0, 0);
    if (nchunks > 1) load_chunk(1, 1);

    for (int c = 0; c < nchunks; c++) {
        if (c < nchunks - 1) cp_wait1(); else cp_wait0();
        __syncthreads();

        const uint32_t stg = sb0 + (uint32_t)(c & 1) * GSTAGEB;
        const uint32_t sAh = stg, sAl = stg + ATILEB, sBh = stg + 2 * ATILEB;

#pragma unroll
        for (int ks = 0; ks < 4; ks++) {
            const uint32_t kbyte = (uint32_t)(ks * 32);

            uint32_t ah[2][4], al[2][4];
#pragma unroll
            for (int mt = 0; mt < 2; mt++) {
                uint32_t rbase = (uint32_t)(wm * 32 + mt * 16) * PITB + aoff + kbyte;
                ldm_x4(ah[mt][0], ah[mt][1], ah[mt][2], ah[mt][3], sAh + rbase);
                ldm_x4(al[mt][0], al[mt][1], al[mt][2], al[mt][3], sAl + rbase);
            }

#pragma unroll
            for (int half = 0; half < 2; half++) {
                uint32_t bh[4][2];
#pragma unroll
                for (int p = 0; p < 2; p++) {
                    uint32_t nb = (uint32_t)(wn * 64 + half * 32 + p * 16) * PITB + boff + kbyte;
                    ldm_x4(bh[2*p][0], bh[2*p][1], bh[2*p+1][0], bh[2*p+1][1], sBh + nb);
                }
#pragma unroll
                for (int mt = 0; mt < 2; mt++)
#pragma unroll
                    for (int nt = 0; nt < 4; nt++) {
                        float* cc = acc[mt][half * 4 + nt];
                        mma_f16(cc, ah[mt], bh[nt]);   // hi * Whi
                        mma_f16(cc, al[mt], bh[nt]);   // lo * Whi
                    }
            }
        }
        __syncthreads();
        if (c + 2 < nchunks) load_chunk(c + 2, c & 1);
    }

    const int g = lane >> 2, t = lane & 3;
#pragma unroll
    for (int mt = 0; mt < 2; mt++) {
        const int row0 = m0 + wm * 32 + mt * 16 + g;
#pragma unroll
        for (int nt = 0; nt < 8; nt++) {
            const int cl = wn * 64 + nt * 8 + 2 * t;
            float2 v0, v1;
            v0.x = acc[mt][nt][0] + sbias[cl];
            v0.y = acc[mt][nt][1] + sbias[cl + 1];
            v1.x = acc[mt][nt][2] + sbias[cl];
            v1.y = acc[mt][nt][3] + sbias[cl + 1];
            *(float2*)&C[(size_t)row0 * GG + n0 + cl] = v0;
            *(float2*)&C[(size_t)(row0 + 8) * GG + n0 + cl] = v1;
        }
    }
}

// ---------------- tensorized bidirectional LSTM recurrence ----------------
// 64 batch rows/CTA, 1 direction. Full W_hh (hi fp16, 512x128 padded) resident
// in SMEM; h = hi+lo fp16 in SMEM. A(h) fragments reused across all 4 gates.
// Only 2 syncthreads per timestep.
#define HPITB 272                         // smem row pitch bytes (136 halves)
#define WREGB (512 * HPITB)               // 139264 bytes: whole W_hh hi
#define RECSMEM (WREGB + 2 * 64 * HPITB)  // +34816 = 174080
__global__ __launch_bounds__(256, 1) void lstm_rec_mma(
    const float* __restrict__ xp_f, const float* __restrict__ xp_b,
    const __half* __restrict__ whh_hi_base,   // 2 dirs, each [512][128]
    float* __restrict__ out32,
    __half* __restrict__ ohi, __half* __restrict__ olo)
{
    extern __shared__ __half smr[];
    const uint32_t sb = smem_u32(smr);
    const uint32_t wB  = sb;
    const uint32_t hHi = sb + WREGB;
    const uint32_t hLo = hHi + 64 * HPITB;

    const int dir = blockIdx.y;
    const float* xp = dir ? xp_b : xp_f;
    const __half* whh_hi = whh_hi_base + (size_t)dir * GG * HH;

    const int tid  = threadIdx.x;
    const int wid  = tid >> 5;
    const int lane = tid & 31;
    const int wm   = wid & 1;        // M half (32 rows)
    const int wn   = wid >> 1;       // 0..3 -> hidden col group of 32
    const int b0   = blockIdx.x * 64;
    const int g4   = lane >> 2;
    const int t4   = lane & 3;

    const uint32_t aoff = (uint32_t)(lane & 15) * HPITB + (uint32_t)(lane >> 4) * 16;
    const uint32_t boff = ((uint32_t)((lane & 7) + ((lane >> 4) << 3))) * HPITB
                        + (uint32_t)((lane >> 3) & 1) * 16;

    // load the ENTIRE W_hh (hi) once: 512 rows x 256B -> 8192 cp16
#pragma unroll
    for (int i = 0; i < 32; i++) {
        int idx = tid + i * 256;            // 0..8191
        int row = idx >> 4, seg = idx & 15;
        cp16(wB + (uint32_t)row * HPITB + (uint32_t)seg * 16,
             whh_hi + (size_t)row * HH + seg * 8);
    }
    cp_commit();

    // zero h (hi+lo regions, contiguous 2*64*272 bytes)
    for (int i = tid; i < (2 * 64 * HPITB) / 4; i += 256)
        *(uint32_t*)((char*)smr + WREGB + i * 4) = 0u;
    cp_wait0();
    __syncthreads();

    float cst[2][4][4];
#pragma unroll
    for (int mt = 0; mt < 2; mt++)
#pragma unroll
        for (int nt = 0; nt < 4; nt++)
#pragma unroll
            for (int e = 0; e < 4; e++) cst[mt][nt][e] = 0.0f;

    float acc[4][2][4][4];

    for (int s = 0; s < TT; s++) {
        const int t = dir ? (TT - 1 - s) : s;

        // init accumulators from xproj (biases pre-folded by GEMM epilogue)
#pragma unroll
        for (int gate = 0; gate < 4; gate++)
#pragma unroll
            for (int mt = 0; mt < 2; mt++) {
                const int r = wm * 32 + mt * 16 + g4;
                const size_t base0 = ((size_t)(b0 + r) * TT + t) * GG + gate * 128;
                const size_t base1 = ((size_t)(b0 + r + 8) * TT + t) * GG + gate * 128;
#pragma unroll
                for (int nt = 0; nt < 4; nt++) {
                    const int j = wn * 32 + nt * 8 + 2 * t4;
                    float2 v0 = *(const float2*)&xp[base0 + j];
                    float2 v1 = *(const float2*)&xp[base1 + j];
                    acc[gate][mt][nt][0] = v0.x; acc[gate][mt][nt][1] = v0.y;
                    acc[gate][mt][nt][2] = v1.x; acc[gate][mt][nt][3] = v1.y;
                }
            }

        // gates += h_prev @ W_hh^T : A(h) frags loaded once per ks, reused x4 gates
#pragma unroll
        for (int ks = 0; ks < 8; ks++) {
            const uint32_t kb = (uint32_t)(ks * 32);
            uint32_t ah[2][4], al[2][4];
#pragma unroll
            for (int mt = 0; mt < 2; mt++) {
                uint32_t rb = (uint32_t)(wm * 32 + mt * 16) * HPITB + aoff + kb;
                ldm_x4(ah[mt][0], ah[mt][1], ah[mt][2], ah[mt][3], hHi + rb);
                ldm_x4(al[mt][0], al[mt][1], al[mt][2], al[mt][3], hLo + rb);
            }
#pragma unroll
            for (int gate = 0; gate < 4; gate++) {
                uint32_t bh[4][2];
#pragma unroll
                for (int p = 0; p < 2; p++) {
                    uint32_t nb = (uint32_t)(gate * 128 + wn * 32 + p * 16) * HPITB + boff + kb;
                    ldm_x4(bh[2*p][0], bh[2*p][1], bh[2*p+1][0], bh[2*p+1][1], wB + nb);
                }
#pragma unroll
                for (int mt = 0; mt < 2; mt++)
#pragma unroll
                    for (int nt = 0; nt < 4; nt++) {
                        float* cc = acc[gate][mt][nt];
                        mma_f16(cc, ah[mt], bh[nt]);
                        mma_f16(cc, al[mt], bh[nt]);
                    }
            }
        }
        __syncthreads();   // all h reads complete before overwrite

        // activations + cell update + h emit
#pragma unroll
        for (int mt = 0; mt < 2; mt++) {
            const int r = wm * 32 + mt * 16 + g4;
#pragma unroll
            for (int nt = 0; nt < 4; nt++) {
                const int j = wn * 32 + nt * 8 + 2 * t4;
                float hv[4];
#pragma unroll
                for (int e = 0; e < 4; e++) {
                    float ig = fsig(acc[0][mt][nt][e]);
                    float fg = fsig(acc[1][mt][nt][e]);
                    float gg = ftanh(acc[2][mt][nt][e]);
                    float og = fsig(acc[3][mt][nt][e]);
                    float cc = fg * cst[mt][nt][e] + ig * gg;
                    cst[mt][nt][e] = cc;
                    hv[e] = og * ftanh(cc);
                }
                __half h0x = __float2half_rn(hv[0]);
                __half h0y = __float2half_rn(hv[1]);
                __half h1x = __float2half_rn(hv[2]);
                __half h1y = __float2half_rn(hv[3]);
                __half2 hp0 = __halves2half2(h0x, h0y);
                __half2 hp1 = __halves2half2(h1x, h1y);
                __half2 lp0 = __halves2half2(__float2half_rn(hv[0] - __half2float(h0x)),
                                             __float2half_rn(hv[1] - __half2float(h0y)));
                __half2 lp1 = __halves2half2(__float2half_rn(hv[2] - __half2float(h1x)),
                                             __float2half_rn(hv[3] - __half2float(h1y)));
                uint32_t uh0 = *reinterpret_cast<uint32_t*>(&hp0);
                uint32_t uh1 = *reinterpret_cast<uint32_t*>(&hp1);
                uint32_t ul0 = *reinterpret_cast<uint32_t*>(&lp0);
                uint32_t ul1 = *reinterpret_cast<uint32_t*>(&lp1);

                // smem h for next step
                *(uint32_t*)((char*)smr + (hHi - sb) + r * HPITB + j * 2) = uh0;
                *(uint32_t*)((char*)smr + (hHi - sb) + (r + 8) * HPITB + j * 2) = uh1;
                *(uint32_t*)((char*)smr + (hLo - sb) + r * HPITB + j * 2) = ul0;
                *(uint32_t*)((char*)smr + (hLo - sb) + (r + 8) * HPITB + j * 2) = ul1;

                // gmem output
                const size_t ob0 = ((size_t)(b0 + r) * TT + t) * (2 * HH) + dir * HH + j;
                const size_t ob1 = ((size_t)(b0 + r + 8) * TT + t) * (2 * HH) + dir * HH + j;
                if (out32) {
                    *(float2*)&out32[ob0] = make_float2(hv[0], hv[1]);
                    *(float2*)&out32[ob1] = make_float2(hv[2], hv[3]);
                } else {
                    *(uint32_t*)&ohi[ob0] = uh0;
                    *(uint32_t*)&ohi[ob1] = uh1;
                    *(uint32_t*)&olo[ob0] = ul0;
                    *(uint32_t*)&olo[ob1] = ul1;
                }
            }
        }
        __syncthreads();   // h writes visible before next step's reads
    }
}

// ---------------- fused maxpool(T) + FC(512->64) + ReLU + FC(64->1) -------
#define W1PITCH 517
__global__ __launch_bounds__(256) void pool_fc(
    const float* __restrict__ o2,
    const float* __restrict__ fc1w, const float* __restrict__ fc1b,
    const float* __restrict__ fc2w, const float* __restrict__ fc2b,
    float* __restrict__ y, int rows_per_warp)
{
    extern __shared__ float smf[];
    float* w1    = smf;
    float* feats = smf + 64 * W1PITCH;

    for (int i = threadIdx.x; i < 64 * 512; i += 256) {
        int j = i >> 9, f = i & 511;
        w1[j * W1PITCH + f] = fc1w[i];
    }
    __syncthreads();

    const int wid  = threadIdx.x >> 5;
    const int lane = threadIdx.x & 31;
    float* myfeat = feats + wid * 512;

    for (int it = 0; it < rows_per_warp; it++) {
        int b = blockIdx.x * (8 * rows_per_warp) + it * 8 + wid;

#pragma unroll
        for (int q = 0; q < 8; q++) {
            int cc = lane + q * 32;
            float m0 = -3.4e38f, m1 = -3.4e38f;
#pragma unroll
            for (int t = 0; t < 5; t++)
                m0 = fmaxf(m0, o2[((size_t)b * TT + t) * (2 * HH) + cc]);
#pragma unroll
            for (int t = 5; t < 10; t++)
                m1 = fmaxf(m1, o2[((size_t)b * TT + t) * (2 * HH) + cc]);
            myfeat[cc * 2 + 0] = m0;
            myfeat[cc * 2 + 1] = m1;
        }
        __syncwarp();

        float a0 = fc1b[lane];
        float a1 = fc1b[lane + 32];
        const float* wr0 = &w1[lane * W1PITCH];
        const float* wr1 = &w1[(lane + 32) * W1PITCH];
#pragma unroll 8
        for (int f = 0; f < 512; f++) {
            float v = myfeat[f];
            a0 += v * wr0[f];
            a1 += v * wr1[f];
        }
        a0 = fmaxf(a0, 0.0f);
        a1 = fmaxf(a1, 0.0f);

        float p = a0 * fc2w[lane] + a1 * fc2w[lane + 32];
#pragma unroll
        for (int off = 16; off; off >>= 1)
            p += __shfl_down_sync(0xffffffffu, p, off);
        if (lane == 0) y[b] = p + fc2b[0];
        __syncwarp();
    }
}

// ---------------- launch ----------------
extern "C" void kernel_launch(void* const* d_in, const int* in_sizes, int n_in,
                              void* d_out, int out_size)
{
    const float* x       = (const float*)d_in[0];
    const float* w_ih1_f = (const float*)d_in[1];
    const float* w_hh1_f = (const float*)d_in[2];
    const float* b_ih1_f = (const float*)d_in[3];
    const float* b_hh1_f = (const float*)d_in[4];
    const float* w_ih1_b = (const float*)d_in[5];
    const float* w_hh1_b = (const float*)d_in[6];
    const float* b_ih1_b = (const float*)d_in[7];
    const float* b_hh1_b = (const float*)d_in[8];
    const float* w_ih2_f = (const float*)d_in[9];
    const float* w_hh2_f = (const float*)d_in[10];
    const float* b_ih2_f = (const float*)d_in[11];
    const float* b_hh2_f = (const float*)d_in[12];
    const float* w_ih2_b = (const float*)d_in[13];
    const float* w_hh2_b = (const float*)d_in[14];
    const float* b_ih2_b = (const float*)d_in[15];
    const float* b_hh2_b = (const float*)d_in[16];
    const float* fc1_w   = (const float*)d_in[17];
    const float* fc1_b   = (const float*)d_in[18];
    const float* fc2_w   = (const float*)d_in[19];
    const float* fc2_b   = (const float*)d_in[20];
    float* y = (float*)d_out;

    float *xpf, *xpb, *o2;
    __half *xhi, *xlo, *ohi, *olo, *whi, *whhhi;
    cudaGetSymbolAddress((void**)&xpf, g_xpf);
    cudaGetSymbolAddress((void**)&xpb, g_xpb);
    cudaGetSymbolAddress((void**)&o2,  g_o2);
    cudaGetSymbolAddress((void**)&xhi, g_xhi);
    cudaGetSymbolAddress((void**)&xlo, g_xlo);
    cudaGetSymbolAddress((void**)&ohi, g_ohi);
    cudaGetSymbolAddress((void**)&olo, g_olo);
    cudaGetSymbolAddress((void**)&whi, g_whi);
    cudaGetSymbolAddress((void**)&whhhi, g_whhhi);

    const int poolSmem = (64 * W1PITCH + 8 * 512) * 4;
    cudaFuncSetAttribute(pool_fc,  cudaFuncAttributeMaxDynamicSharedMemorySize, poolSmem);
    cudaFuncSetAttribute(gemm_mma, cudaFuncAttributeMaxDynamicSharedMemorySize, GEMMSMEM);
    cudaFuncSetAttribute(lstm_rec_mma, cudaFuncAttributeMaxDynamicSharedMemorySize, RECSMEM);

    const size_t WSLOT = (size_t)GG * K2P;
    const size_t HSLOT = (size_t)GG * HH;
    dim3 gemmGrid(GG / 128, MM / 128);   // (4, 1280): N fastest -> A L2 reuse
    dim3 recGrid(BB / 64, 2);

    // 0) x split, 1-2) layer-1 w_ih hi
    convert_split<<<16384, 256>>>(x, xhi, xlo, MM, II, K1P);
    convert_h<<<512, 256>>>(w_ih1_f, whi + 0 * WSLOT, GG, II, K1P);
    convert_h<<<512, 256>>>(w_ih1_b, whi + 1 * WSLOT, GG, II, K1P);

    // 3-4) layer 1 xproj — launch index 4 is the ncu capture target
    gemm_mma<<<gemmGrid, 256, GEMMSMEM>>>(xhi, xlo, whi + 0 * WSLOT,
                                          K1P, 3, b_ih1_f, b_hh1_f, xpf);
    gemm_mma<<<gemmGrid, 256, GEMMSMEM>>>(xhi, xlo, whi + 1 * WSLOT,
                                          K1P, 3, b_ih1_b, b_hh1_b, xpb);

    // 5-10) remaining weight conversions
    convert_h<<<256, 256>>>(w_hh1_f, whhhi + 0 * HSLOT, GG, HH, HH);
    convert_h<<<256, 256>>>(w_hh1_b, whhhi + 1 * HSLOT, GG, HH, HH);
    convert_h<<<512, 256>>>(w_ih2_f, whi + 2 * WSLOT, GG, 2 * HH, K2P);
    convert_h<<<512, 256>>>(w_ih2_b, whi + 3 * WSLOT, GG, 2 * HH, K2P);
    convert_h<<<256, 256>>>(w_hh2_f, whhhi + 2 * HSLOT, GG, HH, HH);
    convert_h<<<256, 256>>>(w_hh2_b, whhhi + 3 * HSLOT, GG, HH, HH);

    // 11) layer 1 recurrence -> fp16 hi/lo for layer-2 GEMM A
    lstm_rec_mma<<<recGrid, 256, RECSMEM>>>(xpf, xpb, whhhi,
                                            (float*)nullptr, ohi, olo);

    // 12-13) layer 2 xproj (K=256)
    gemm_mma<<<gemmGrid, 256, GEMMSMEM>>>(ohi, olo, whi + 2 * WSLOT,
                                          K2P, 4, b_ih2_f, b_hh2_f, xpf);
    gemm_mma<<<gemmGrid, 256, GEMMSMEM>>>(ohi, olo, whi + 3 * WSLOT,
                                          K2P, 4, b_ih2_b, b_hh2_b, xpb);

    // 14) layer 2 recurrence -> fp32 output
    lstm_rec_mma<<<recGrid, 256, RECSMEM>>>(xpf, xpb, whhhi + 2 * HSLOT,
                                            o2, (__half*)nullptr, (__half*)nullptr);

    // 15) pool + FC head
    pool_fc<<<256, 256, poolSmem>>>(o2, fc1_w, fc1_b, fc2_w, fc2_b, y, 8);
}